// round 4
// baseline (speedup 1.0000x reference)
#include <cuda_runtime.h>
#include <cuda_bf16.h>
#include <math.h>

#define T_TOK 4096
#define DIM   2048
#define NEXP  16
#define FDIM  768

// One block = one token. 256 threads = 8 warps.
// No device globals, no atomics, no cross-kernel state.
__global__ __launch_bounds__(256)
void moe_token_kernel(const float* __restrict__ x,
                      const float* __restrict__ rw,
                      const float* __restrict__ gw,
                      const float* __restrict__ uw,
                      const float* __restrict__ dw,
                      float* __restrict__ out,
                      float* __restrict__ logits_out,
                      int write_logits) {
    __shared__ float xs[DIM];    // token activations
    __shared__ float hs[FDIM];   // weighted SwiGLU hidden
    __shared__ float os[DIM];    // output accumulator
    __shared__ float lg[NEXP];
    __shared__ int   se[2];
    __shared__ float sw[2];

    const int t = blockIdx.x;
    const int tid = threadIdx.x;
    const int warp = tid >> 5, lane = tid & 31;

    // ---- load x[t] into smem, zero output accumulator ----
    const float4* xg = (const float4*)(x + (size_t)t * DIM);
    for (int i = tid; i < DIM / 4; i += 256) ((float4*)xs)[i] = xg[i];
    for (int i = tid; i < DIM; i += 256) os[i] = 0.0f;
    __syncthreads();

    // ---- router: warp w computes logits for experts 2w, 2w+1 ----
    {
        const float4* w0 = (const float4*)(rw + (size_t)(warp * 2) * DIM);
        const float4* w1 = (const float4*)(rw + (size_t)(warp * 2 + 1) * DIM);
        float a0 = 0.f, a1 = 0.f;
        for (int i = lane; i < DIM / 4; i += 32) {
            const float4 xv = ((const float4*)xs)[i];
            const float4 va = w0[i];
            const float4 vb = w1[i];
            a0 += xv.x * va.x + xv.y * va.y + xv.z * va.z + xv.w * va.w;
            a1 += xv.x * vb.x + xv.y * vb.y + xv.z * vb.z + xv.w * vb.w;
        }
        #pragma unroll
        for (int o = 16; o > 0; o >>= 1) {
            a0 += __shfl_xor_sync(0xffffffffu, a0, o);
            a1 += __shfl_xor_sync(0xffffffffu, a1, o);
        }
        if (lane == 0) { lg[warp * 2] = a0; lg[warp * 2 + 1] = a1; }
    }
    __syncthreads();

    if (write_logits && tid < NEXP)
        logits_out[(size_t)t * NEXP + tid] = lg[tid];

    if (tid == 0) {
        int i0 = 0;
        #pragma unroll
        for (int i = 1; i < NEXP; i++)
            if (lg[i] > lg[i0]) i0 = i;
        int i1 = (i0 == 0) ? 1 : 0;
        #pragma unroll
        for (int i = 0; i < NEXP; i++) {
            if (i == i0) continue;
            if (lg[i] > lg[i1]) i1 = i;
        }
        // normalized top-2 softmax weights (softmax denominator cancels)
        const float e1 = __expf(lg[i1] - lg[i0]);
        const float s = 1.0f + e1;
        se[0] = i0; sw[0] = 1.0f / s;
        se[1] = i1; sw[1] = e1 / s;
    }
    __syncthreads();

    // ---- two experts ----
    for (int k = 0; k < 2; k++) {
        const int e = se[k];
        const float wt = sw[k];
        const float* gbase = gw + (size_t)e * FDIM * DIM;
        const float* ubase = uw + (size_t)e * FDIM * DIM;

        // Phase A: hs[f] = wt * silu(gate_f . x) * (up_f . x); warp per f-row
        for (int f = warp; f < FDIM; f += 8) {
            const float4* gr = (const float4*)(gbase + (size_t)f * DIM);
            const float4* ur = (const float4*)(ubase + (size_t)f * DIM);
            float ag = 0.f, au = 0.f;
            for (int i = lane; i < DIM / 4; i += 32) {
                const float4 xv = ((const float4*)xs)[i];
                const float4 gv = gr[i];
                const float4 uv = ur[i];
                ag += xv.x * gv.x + xv.y * gv.y + xv.z * gv.z + xv.w * gv.w;
                au += xv.x * uv.x + xv.y * uv.y + xv.z * uv.z + xv.w * uv.w;
            }
            #pragma unroll
            for (int o = 16; o > 0; o >>= 1) {
                ag += __shfl_xor_sync(0xffffffffu, ag, o);
                au += __shfl_xor_sync(0xffffffffu, au, o);
            }
            if (lane == 0) {
                const float sig = 1.0f / (1.0f + __expf(-ag));
                hs[f] = wt * (ag * sig) * au;
            }
        }
        __syncthreads();

        // Phase B: os[d] += down_e[d] . hs; warp per d-row
        const float* dbase = dw + (size_t)e * DIM * FDIM;
        for (int d = warp; d < DIM; d += 8) {
            const float4* dr = (const float4*)(dbase + (size_t)d * FDIM);
            float a = 0.f;
            #pragma unroll
            for (int i = lane; i < FDIM / 4; i += 32) {   // 6 iterations
                const float4 dv = dr[i];
                const float4 hv = ((const float4*)hs)[i];
                a += dv.x * hv.x + dv.y * hv.y + dv.z * hv.z + dv.w * hv.w;
            }
            #pragma unroll
            for (int o = 16; o > 0; o >>= 1)
                a += __shfl_xor_sync(0xffffffffu, a, o);
            if (lane == 0) os[d] += a;
        }
        __syncthreads();   // protects hs before next expert overwrites it
    }

    // ---- write out[t] ----
    float4* og = (float4*)(out + (size_t)t * DIM);
    for (int i = tid; i < DIM / 4; i += 256) og[i] = ((const float4*)os)[i];
}

extern "C" void kernel_launch(void* const* d_in, const int* in_sizes, int n_in,
                              void* d_out, int out_size) {
    // Classify inputs by RELATIVE size (unit-invariant: elements or bytes):
    // the three equal-largest = expert weights; larger remainder = hidden; smallest = router.
    long long smax = -1;
    for (int i = 0; i < n_in; i++)
        if ((long long)in_sizes[i] > smax) smax = in_sizes[i];
    const float* w3[3] = {0, 0, 0};
    int wpos[3] = {-1, -1, -1};
    int nw = 0, ih = -1, irt = -1;
    for (int i = 0; i < n_in; i++)
        if ((long long)in_sizes[i] == smax && nw < 3) { w3[nw] = (const float*)d_in[i]; wpos[nw] = i; nw++; }
    long long best_h = -1;
    for (int i = 0; i < n_in; i++) {
        if (i == wpos[0] || i == wpos[1] || i == wpos[2]) continue;
        if ((long long)in_sizes[i] > best_h) { best_h = in_sizes[i]; ih = i; }
    }
    long long best_r = (long long)1 << 62;
    for (int i = 0; i < n_in; i++) {
        if (i == wpos[0] || i == wpos[1] || i == wpos[2] || i == ih) continue;
        if ((long long)in_sizes[i] < best_r) { best_r = in_sizes[i]; irt = i; }
    }
    const float* x  = (ih  >= 0) ? (const float*)d_in[ih]  : (const float*)d_in[0];
    const float* rw = (irt >= 0) ? (const float*)d_in[irt] : (const float*)d_in[1];
    const float *gw, *uw, *dw;
    if (nw == 3) {
        if (ih == 2) { dw = w3[0]; gw = w3[1]; uw = w3[2]; }   // alphabetical file order
        else         { gw = w3[0]; uw = w3[1]; dw = w3[2]; }   // signature order
    } else {
        x  = (const float*)d_in[0]; rw = (const float*)d_in[1];
        gw = (const float*)d_in[2]; uw = (const float*)d_in[3]; dw = (const float*)d_in[4];
    }
    float* out = (float*)d_out;

    const int need = T_TOK * DIM + T_TOK * NEXP;
    const int write_logits = (out_size >= need) ? 1 : 0;
    float* logits = out + (size_t)T_TOK * DIM;

    moe_token_kernel<<<T_TOK, 256>>>(x, rw, gw, uw, dw, out, logits, write_logits);
}

// round 7
// speedup vs baseline: 2.5059x; 2.5059x over previous
#include <cuda_runtime.h>
#include <cuda_bf16.h>
#include <math.h>

#define T_TOK 4096
#define DIM   2048
#define NEXP  16
#define FDIM  768
#define NSLOT (T_TOK * 2)   // T * TOP_K
#define MTILES 64           // max 128-row tiles per expert (covers worst skew)

// ---------------- device scratch; accessed ONLY via device-code symbol references ----------------
__device__ __align__(16) int   g_off[NEXP + 1];
__device__ __align__(16) int   g_tok_e[NSLOT];
__device__ __align__(16) float g_tok_w[NSLOT];
__device__ __align__(16) int   g_perm[NSLOT];      // slot -> token
__device__ __align__(16) float g_wt[NSLOT];        // slot -> combine weight
__device__ __align__(16) float g_G[(size_t)NSLOT * FDIM];   // raw gate proj
__device__ __align__(16) float g_U[(size_t)NSLOT * FDIM];   // raw up proj

// ---------------- zero the output region ----------------
__global__ void zero_out_kernel(float* __restrict__ out) {
    const size_t i = (size_t)blockIdx.x * blockDim.x + threadIdx.x;
    if (i < (size_t)T_TOK * DIM / 4)
        ((float4*)out)[i] = make_float4(0.f, 0.f, 0.f, 0.f);
}

// ---------------- router (proven round-4 core) ----------------
__global__ __launch_bounds__(256)
void router_kernel(const float* __restrict__ x,
                   const float* __restrict__ rw,
                   float* __restrict__ logits_out,
                   int write_logits) {
    __shared__ float xs[DIM];
    __shared__ float lg[NEXP];
    const int t = blockIdx.x;
    const int tid = threadIdx.x;
    const int warp = tid >> 5, lane = tid & 31;

    const float4* xg = (const float4*)(x + (size_t)t * DIM);
    for (int i = tid; i < DIM / 4; i += 256) ((float4*)xs)[i] = xg[i];
    __syncthreads();

    {
        const float4* w0 = (const float4*)(rw + (size_t)(warp * 2) * DIM);
        const float4* w1 = (const float4*)(rw + (size_t)(warp * 2 + 1) * DIM);
        float a0 = 0.f, a1 = 0.f;
        for (int i = lane; i < DIM / 4; i += 32) {
            const float4 xv = ((const float4*)xs)[i];
            const float4 va = w0[i];
            const float4 vb = w1[i];
            a0 += xv.x * va.x + xv.y * va.y + xv.z * va.z + xv.w * va.w;
            a1 += xv.x * vb.x + xv.y * vb.y + xv.z * vb.z + xv.w * vb.w;
        }
        #pragma unroll
        for (int o = 16; o > 0; o >>= 1) {
            a0 += __shfl_xor_sync(0xffffffffu, a0, o);
            a1 += __shfl_xor_sync(0xffffffffu, a1, o);
        }
        if (lane == 0) { lg[warp * 2] = a0; lg[warp * 2 + 1] = a1; }
    }
    __syncthreads();

    if (write_logits && tid < NEXP)
        logits_out[(size_t)t * NEXP + tid] = lg[tid];

    if (tid == 0) {
        int i0 = 0;
        #pragma unroll
        for (int i = 1; i < NEXP; i++)
            if (lg[i] > lg[i0]) i0 = i;
        int i1 = (i0 == 0) ? 1 : 0;
        #pragma unroll
        for (int i = 0; i < NEXP; i++) {
            if (i == i0) continue;
            if (lg[i] > lg[i1]) i1 = i;
        }
        const float e1 = __expf(lg[i1] - lg[i0]);
        const float s = 1.0f + e1;
        g_tok_e[2 * t + 0] = i0; g_tok_w[2 * t + 0] = 1.0f / s;
        g_tok_e[2 * t + 1] = i1; g_tok_w[2 * t + 1] = e1 / s;
    }
}

// ---------------- single-block: histogram + scan + ordered compaction ----------------
__global__ void route_build_kernel() {
    __shared__ int s_cnt[NEXP];
    __shared__ int s_off[NEXP + 1];
    const int tid = threadIdx.x;           // 512 threads
    if (tid < NEXP) s_cnt[tid] = 0;
    __syncthreads();
    for (int i = tid; i < NSLOT; i += 512)
        atomicAdd(&s_cnt[g_tok_e[i] & (NEXP - 1)], 1);
    __syncthreads();
    if (tid == 0) {
        int off = 0;
        #pragma unroll
        for (int e = 0; e < NEXP; e++) { s_off[e] = off; g_off[e] = off; off += s_cnt[e]; }
        s_off[NEXP] = off; g_off[NEXP] = off;
    }
    __syncthreads();
    const int warp = tid >> 5, lane = tid & 31;  // 16 warps, one per expert
    int base = s_off[warp];
    for (int i0 = 0; i0 < NSLOT; i0 += 32) {
        const int i = i0 + lane;
        const bool m = ((g_tok_e[i] & (NEXP - 1)) == warp);
        const unsigned mask = __ballot_sync(0xffffffffu, m);
        if (m) {
            const int pos = base + __popc(mask & ((1u << lane) - 1u));
            if (pos < NSLOT) {
                g_perm[pos] = i >> 1;
                g_wt[pos]   = g_tok_w[i];
            }
        }
        base += __popc(mask);
    }
}

// ---------------- gather GEMM (gate/up): writes g_G (DST=0) or g_U (DST=1) via device symbol ----------------
template <int DST>
__global__ __launch_bounds__(256)
void gemm_gather_kernel(const float* __restrict__ A,   // x [T, DIM]
                        const float* __restrict__ W) { // [E, FDIM, DIM]
    const int BM = 128, BN = 128, BK = 16, Kd = DIM, N = FDIM;
    float* __restrict__ C = (DST == 0) ? g_G : g_U;    // device-side symbol address
    const int e  = blockIdx.y / MTILES;
    const int mt = blockIdx.y % MTILES;
    if (e >= NEXP) return;
    int segBeg = g_off[e], segEnd = g_off[e + 1];
    if (segBeg < 0) segBeg = 0;
    if (segEnd > NSLOT) segEnd = NSLOT;
    const int m0 = segBeg + mt * BM;
    if (m0 >= segEnd) return;
    const int mrem = segEnd - m0;
    const int n0 = blockIdx.x * BN;

    __shared__ float As[BK][BM];
    __shared__ float Bs[BK][BN];

    const int tid = threadIdx.x;
    const int tx = tid & 15, ty = tid >> 4;

    const float* aptr[2];
    #pragma unroll
    for (int j = 0; j < 2; j++) {
        const int idx = 2 * tid + j;
        const int r = idx >> 2;
        const bool valid = (r < mrem);
        long grow = 0;
        if (valid) {
            grow = (long)g_perm[m0 + r];
            if (grow < 0) grow = 0;
            if (grow >= T_TOK) grow = T_TOK - 1;
        }
        aptr[j] = valid ? (A + grow * (long)Kd + (idx & 3) * 4) : (const float*)0;
    }
    const float* wbase = W + ((size_t)e * N + n0) * (size_t)Kd;

    float acc[8][8];
    #pragma unroll
    for (int i = 0; i < 8; i++)
        #pragma unroll
        for (int j = 0; j < 8; j++) acc[i][j] = 0.f;

    for (int k0 = 0; k0 < Kd; k0 += BK) {
        #pragma unroll
        for (int j = 0; j < 2; j++) {
            const int idx = 2 * tid + j;
            const int r = idx >> 2, c4 = idx & 3;
            float4 v = make_float4(0.f, 0.f, 0.f, 0.f);
            if (aptr[j]) v = *(const float4*)(aptr[j] + k0);
            As[c4 * 4 + 0][r] = v.x;
            As[c4 * 4 + 1][r] = v.y;
            As[c4 * 4 + 2][r] = v.z;
            As[c4 * 4 + 3][r] = v.w;
            const float4 w4 = *(const float4*)(wbase + (size_t)r * Kd + k0 + c4 * 4);
            Bs[c4 * 4 + 0][r] = w4.x;
            Bs[c4 * 4 + 1][r] = w4.y;
            Bs[c4 * 4 + 2][r] = w4.z;
            Bs[c4 * 4 + 3][r] = w4.w;
        }
        __syncthreads();
        #pragma unroll
        for (int kk = 0; kk < BK; kk++) {
            float a[8], b[8];
            *(float4*)&a[0] = *(const float4*)&As[kk][ty * 8];
            *(float4*)&a[4] = *(const float4*)&As[kk][ty * 8 + 4];
            *(float4*)&b[0] = *(const float4*)&Bs[kk][tx * 8];
            *(float4*)&b[4] = *(const float4*)&Bs[kk][tx * 8 + 4];
            #pragma unroll
            for (int i = 0; i < 8; i++)
                #pragma unroll
                for (int j = 0; j < 8; j++)
                    acc[i][j] += a[i] * b[j];
        }
        __syncthreads();
    }

    #pragma unroll
    for (int i = 0; i < 8; i++) {
        const int r = ty * 8 + i;
        if (r < mrem) {
            float* crow = C + (size_t)(m0 + r) * N + n0 + tx * 8;
            *(float4*)(crow + 0) = make_float4(acc[i][0], acc[i][1], acc[i][2], acc[i][3]);
            *(float4*)(crow + 4) = make_float4(acc[i][4], acc[i][5], acc[i][6], acc[i][7]);
        }
    }
}

// ---------------- down GEMM: SwiGLU fused into A-load; scatter-add into out ----------------
// out[perm[slot], n] += ( wt[slot] * silu(G[slot,:]) * U[slot,:] ) . dw[e][n][:]
__global__ __launch_bounds__(256)
void gemm_down_kernel(const float* __restrict__ W,    // dw [E, DIM, FDIM]
                      float* __restrict__ out) {
    const int BM = 128, BN = 128, BK = 16, Kd = FDIM, N = DIM;
    const int e  = blockIdx.y / MTILES;
    const int mt = blockIdx.y % MTILES;
    if (e >= NEXP) return;
    int segBeg = g_off[e], segEnd = g_off[e + 1];
    if (segBeg < 0) segBeg = 0;
    if (segEnd > NSLOT) segEnd = NSLOT;
    const int m0 = segBeg + mt * BM;
    if (m0 >= segEnd) return;
    const int mrem = segEnd - m0;
    const int n0 = blockIdx.x * BN;

    __shared__ float As[BK][BM];
    __shared__ float Bs[BK][BN];

    const int tid = threadIdx.x;
    const int tx = tid & 15, ty = tid >> 4;

    const float* pg[2];
    const float* pu[2];
    float wtv[2];
    #pragma unroll
    for (int j = 0; j < 2; j++) {
        const int idx = 2 * tid + j;
        const int r = idx >> 2;
        const bool valid = (r < mrem);
        const long slot = valid ? (long)(m0 + r) : 0;
        pg[j]  = valid ? (g_G + slot * FDIM + (idx & 3) * 4) : (const float*)0;
        pu[j]  = g_U + slot * FDIM + (idx & 3) * 4;
        wtv[j] = g_wt[slot];
    }
    const float* wbase = W + ((size_t)e * N + n0) * (size_t)Kd;

    float acc[8][8];
    #pragma unroll
    for (int i = 0; i < 8; i++)
        #pragma unroll
        for (int j = 0; j < 8; j++) acc[i][j] = 0.f;

    for (int k0 = 0; k0 < Kd; k0 += BK) {
        #pragma unroll
        for (int j = 0; j < 2; j++) {
            const int idx = 2 * tid + j;
            const int r = idx >> 2, c4 = idx & 3;
            float4 h = make_float4(0.f, 0.f, 0.f, 0.f);
            if (pg[j]) {
                const float4 g = *(const float4*)(pg[j] + k0);
                const float4 u = *(const float4*)(pu[j] + k0);
                const float wt = wtv[j];
                h.x = wt * u.x * (g.x / (1.f + __expf(-g.x)));
                h.y = wt * u.y * (g.y / (1.f + __expf(-g.y)));
                h.z = wt * u.z * (g.z / (1.f + __expf(-g.z)));
                h.w = wt * u.w * (g.w / (1.f + __expf(-g.w)));
            }
            As[c4 * 4 + 0][r] = h.x;
            As[c4 * 4 + 1][r] = h.y;
            As[c4 * 4 + 2][r] = h.z;
            As[c4 * 4 + 3][r] = h.w;
            const float4 w4 = *(const float4*)(wbase + (size_t)r * Kd + k0 + c4 * 4);
            Bs[c4 * 4 + 0][r] = w4.x;
            Bs[c4 * 4 + 1][r] = w4.y;
            Bs[c4 * 4 + 2][r] = w4.z;
            Bs[c4 * 4 + 3][r] = w4.w;
        }
        __syncthreads();
        #pragma unroll
        for (int kk = 0; kk < BK; kk++) {
            float a[8], b[8];
            *(float4*)&a[0] = *(const float4*)&As[kk][ty * 8];
            *(float4*)&a[4] = *(const float4*)&As[kk][ty * 8 + 4];
            *(float4*)&b[0] = *(const float4*)&Bs[kk][tx * 8];
            *(float4*)&b[4] = *(const float4*)&Bs[kk][tx * 8 + 4];
            #pragma unroll
            for (int i = 0; i < 8; i++)
                #pragma unroll
                for (int j = 0; j < 8; j++)
                    acc[i][j] += a[i] * b[j];
        }
        __syncthreads();
    }

    #pragma unroll
    for (int i = 0; i < 8; i++) {
        const int r = ty * 8 + i;
        if (r < mrem) {
            int tok = g_perm[m0 + r];
            if (tok < 0) tok = 0;
            if (tok >= T_TOK) tok = T_TOK - 1;
            float* orow = out + (size_t)tok * N + n0 + tx * 8;
            #pragma unroll
            for (int j = 0; j < 8; j++)
                atomicAdd(orow + j, acc[i][j]);   // exactly 2 commutative adds per element
        }
    }
}

// ---------------- launch ----------------
extern "C" void kernel_launch(void* const* d_in, const int* in_sizes, int n_in,
                              void* d_out, int out_size) {
    long long smax = -1;
    for (int i = 0; i < n_in; i++)
        if ((long long)in_sizes[i] > smax) smax = in_sizes[i];
    const float* w3[3] = {0, 0, 0};
    int wpos[3] = {-1, -1, -1};
    int nw = 0, ih = -1, irt = -1;
    for (int i = 0; i < n_in; i++)
        if ((long long)in_sizes[i] == smax && nw < 3) { w3[nw] = (const float*)d_in[i]; wpos[nw] = i; nw++; }
    long long best_h = -1;
    for (int i = 0; i < n_in; i++) {
        if (i == wpos[0] || i == wpos[1] || i == wpos[2]) continue;
        if ((long long)in_sizes[i] > best_h) { best_h = in_sizes[i]; ih = i; }
    }
    long long best_r = (long long)1 << 62;
    for (int i = 0; i < n_in; i++) {
        if (i == wpos[0] || i == wpos[1] || i == wpos[2] || i == ih) continue;
        if ((long long)in_sizes[i] < best_r) { best_r = in_sizes[i]; irt = i; }
    }
    const float* x  = (ih  >= 0) ? (const float*)d_in[ih]  : (const float*)d_in[0];
    const float* rw = (irt >= 0) ? (const float*)d_in[irt] : (const float*)d_in[1];
    const float *gw, *uw, *dw;
    if (nw == 3) {
        if (ih == 2) { dw = w3[0]; gw = w3[1]; uw = w3[2]; }   // alphabetical file order
        else         { gw = w3[0]; uw = w3[1]; dw = w3[2]; }   // signature order
    } else {
        x  = (const float*)d_in[0]; rw = (const float*)d_in[1];
        gw = (const float*)d_in[2]; uw = (const float*)d_in[3]; dw = (const float*)d_in[4];
    }
    float* out = (float*)d_out;

    const int need = T_TOK * DIM + T_TOK * NEXP;
    const int write_logits = (out_size >= need) ? 1 : 0;
    float* logits = out + (size_t)T_TOK * DIM;

    zero_out_kernel<<<(T_TOK * DIM / 4 + 255) / 256, 256>>>(out);
    router_kernel<<<T_TOK, 256>>>(x, rw, logits, write_logits);
    route_build_kernel<<<1, 512>>>();

    // raw gate and up projections into g_G / g_U (device symbols, never host-passed)
    gemm_gather_kernel<0><<<dim3(FDIM / 128, NEXP * MTILES), 256>>>(x, gw);
    gemm_gather_kernel<1><<<dim3(FDIM / 128, NEXP * MTILES), 256>>>(x, uw);

    // down projection with fused SwiGLU; scatter-add into out
    gemm_down_kernel<<<dim3(DIM / 128, NEXP * MTILES), 256>>>(dw, out);
}

// round 9
// speedup vs baseline: 4.0737x; 1.6256x over previous
#include <cuda_runtime.h>
#include <cuda_bf16.h>
#include <math.h>
#include <stdint.h>

#define T_TOK 4096
#define DIM   2048
#define NEXP  16
#define FDIM  768
#define NSLOT (T_TOK * 2)
#define MTILES 64
#define WSZ ((size_t)NEXP * FDIM * DIM)   // elements per weight matrix

// ---------------- device scratch; NEVER passed as kernel args (ATS host-shadow hazard) ----------------
__device__ __align__(16) int      g_off[NEXP + 1];
__device__ __align__(16) int      g_tok_e[NSLOT];
__device__ __align__(16) float    g_tok_w[NSLOT];
__device__ __align__(16) int      g_perm[NSLOT];
__device__ __align__(16) float    g_wt[NSLOT];
__device__ __align__(16) float    g_G[(size_t)NSLOT * FDIM];   // raw gate proj
__device__ __align__(16) float    g_U[(size_t)NSLOT * FDIM];   // raw up proj
__device__ __align__(16) uint32_t g_Whi[3 * WSZ / 2];          // bf16x2 hi: [gate|up|down]
__device__ __align__(16) uint32_t g_Wlo[3 * WSZ / 2];          // bf16x2 lo

// ---------------- helpers ----------------
__device__ __forceinline__ uint32_t smem_u32(const void* p) {
    uint32_t a;
    asm("{ .reg .u64 t; cvta.to.shared.u64 t, %1; cvt.u32.u64 %0, t; }" : "=r"(a) : "l"(p));
    return a;
}
#define STS128(addr, r0, r1, r2, r3) \
    asm volatile("st.shared.v4.b32 [%0], {%1,%2,%3,%4};" :: "r"(addr), "r"(r0), "r"(r1), "r"(r2), "r"(r3) : "memory")

__device__ __forceinline__ void ldm4(uint32_t* r, uint32_t addr) {
    asm volatile("ldmatrix.sync.aligned.m8n8.x4.shared.b16 {%0,%1,%2,%3}, [%4];"
        : "=r"(r[0]), "=r"(r[1]), "=r"(r[2]), "=r"(r[3]) : "r"(addr));
}
__device__ __forceinline__ void mma16816(float* d, const uint32_t* a, uint32_t b0, uint32_t b1) {
    asm volatile(
        "mma.sync.aligned.m16n8k16.row.col.f32.bf16.bf16.f32 "
        "{%0,%1,%2,%3}, {%4,%5,%6,%7}, {%8,%9}, {%0,%1,%2,%3};"
        : "+f"(d[0]), "+f"(d[1]), "+f"(d[2]), "+f"(d[3])
        : "r"(a[0]), "r"(a[1]), "r"(a[2]), "r"(a[3]), "r"(b0), "r"(b1));
}
__device__ __forceinline__ void split4(float4 v, uint32_t* hi, uint32_t* lo) {
    __nv_bfloat162 h0 = __floats2bfloat162_rn(v.x, v.y);
    __nv_bfloat162 h1 = __floats2bfloat162_rn(v.z, v.w);
    float2 f0 = __bfloat1622float2(h0);
    float2 f1 = __bfloat1622float2(h1);
    __nv_bfloat162 l0 = __floats2bfloat162_rn(v.x - f0.x, v.y - f0.y);
    __nv_bfloat162 l1 = __floats2bfloat162_rn(v.z - f1.x, v.w - f1.y);
    hi[0] = *(uint32_t*)&h0; hi[1] = *(uint32_t*)&h1;
    lo[0] = *(uint32_t*)&l0; lo[1] = *(uint32_t*)&l1;
}

// ---------------- zero output ----------------
__global__ void zero_out_kernel(float* __restrict__ out) {
    const size_t i = (size_t)blockIdx.x * blockDim.x + threadIdx.x;
    if (i < (size_t)T_TOK * DIM / 4)
        ((float4*)out)[i] = make_float4(0.f, 0.f, 0.f, 0.f);
}

// ---------------- weight pre-split: fp32 -> bf16 hi/lo (slice: 0 gate, 1 up, 2 down) ----------------
__global__ void conv_kernel(const float4* __restrict__ src, int slice) {
    const size_t base = (size_t)slice * (WSZ / 2);
    const size_t n4 = WSZ / 4;
    for (size_t i = (size_t)blockIdx.x * blockDim.x + threadIdx.x; i < n4;
         i += (size_t)gridDim.x * blockDim.x) {
        const float4 v = src[i];
        uint32_t hi[2], lo[2];
        split4(v, hi, lo);
        uint2 hu, lu;
        hu.x = hi[0]; hu.y = hi[1];
        lu.x = lo[0]; lu.y = lo[1];
        *(uint2*)&g_Whi[base + 2 * i] = hu;
        *(uint2*)&g_Wlo[base + 2 * i] = lu;
    }
}

// ---------------- router (proven) ----------------
__global__ __launch_bounds__(256)
void router_kernel(const float* __restrict__ x,
                   const float* __restrict__ rw,
                   float* __restrict__ logits_out,
                   int write_logits) {
    __shared__ float xs[DIM];
    __shared__ float lg[NEXP];
    const int t = blockIdx.x;
    const int tid = threadIdx.x;
    const int warp = tid >> 5, lane = tid & 31;

    const float4* xg = (const float4*)(x + (size_t)t * DIM);
    for (int i = tid; i < DIM / 4; i += 256) ((float4*)xs)[i] = xg[i];
    __syncthreads();
    {
        const float4* w0 = (const float4*)(rw + (size_t)(warp * 2) * DIM);
        const float4* w1 = (const float4*)(rw + (size_t)(warp * 2 + 1) * DIM);
        float a0 = 0.f, a1 = 0.f;
        for (int i = lane; i < DIM / 4; i += 32) {
            const float4 xv = ((const float4*)xs)[i];
            const float4 va = w0[i];
            const float4 vb = w1[i];
            a0 += xv.x * va.x + xv.y * va.y + xv.z * va.z + xv.w * va.w;
            a1 += xv.x * vb.x + xv.y * vb.y + xv.z * vb.z + xv.w * vb.w;
        }
        #pragma unroll
        for (int o = 16; o > 0; o >>= 1) {
            a0 += __shfl_xor_sync(0xffffffffu, a0, o);
            a1 += __shfl_xor_sync(0xffffffffu, a1, o);
        }
        if (lane == 0) { lg[warp * 2] = a0; lg[warp * 2 + 1] = a1; }
    }
    __syncthreads();
    if (write_logits && tid < NEXP)
        logits_out[(size_t)t * NEXP + tid] = lg[tid];
    if (tid == 0) {
        int i0 = 0;
        #pragma unroll
        for (int i = 1; i < NEXP; i++)
            if (lg[i] > lg[i0]) i0 = i;
        int i1 = (i0 == 0) ? 1 : 0;
        #pragma unroll
        for (int i = 0; i < NEXP; i++) {
            if (i == i0) continue;
            if (lg[i] > lg[i1]) i1 = i;
        }
        const float e1 = __expf(lg[i1] - lg[i0]);
        const float s = 1.0f + e1;
        g_tok_e[2 * t + 0] = i0; g_tok_w[2 * t + 0] = 1.0f / s;
        g_tok_e[2 * t + 1] = i1; g_tok_w[2 * t + 1] = e1 / s;
    }
}

// ---------------- compaction (proven) ----------------
__global__ void route_build_kernel() {
    __shared__ int s_cnt[NEXP];
    __shared__ int s_off[NEXP + 1];
    const int tid = threadIdx.x;
    if (tid < NEXP) s_cnt[tid] = 0;
    __syncthreads();
    for (int i = tid; i < NSLOT; i += 512)
        atomicAdd(&s_cnt[g_tok_e[i] & (NEXP - 1)], 1);
    __syncthreads();
    if (tid == 0) {
        int off = 0;
        #pragma unroll
        for (int e = 0; e < NEXP; e++) { s_off[e] = off; g_off[e] = off; off += s_cnt[e]; }
        s_off[NEXP] = off; g_off[NEXP] = off;
    }
    __syncthreads();
    const int warp = tid >> 5, lane = tid & 31;
    int base = s_off[warp];
    for (int i0 = 0; i0 < NSLOT; i0 += 32) {
        const int i = i0 + lane;
        const bool m = ((g_tok_e[i] & (NEXP - 1)) == warp);
        const unsigned mask = __ballot_sync(0xffffffffu, m);
        if (m) {
            const int pos = base + __popc(mask & ((1u << lane) - 1u));
            if (pos < NSLOT) {
                g_perm[pos] = i >> 1;
                g_wt[pos]   = g_tok_w[i];
            }
        }
        base += __popc(mask);
    }
}

// ================= mma.sync grouped GEMM =================
// MODE 0: C=g_G = gather(x) @ gate^T    (K=2048, N=768)
// MODE 1: C=g_U = gather(x) @ up^T      (K=2048, N=768)
// MODE 2: out  += swiglu(g_G,g_U,wt) @ down^T, scatter-add (K=768, N=2048)
// Tile: M=128 x N=128, K-chunk 32, bf16 hi/lo 3-term split on HMMA (mma.sync m16n8k16).
// Stage (40960 B): A_hi 0 | A_lo 10240 | B_hi 20480 | B_lo 30720; rows padded to 80 B.
#define MM_SMEM (2 * 40960)

template <int MODE>
__global__ __launch_bounds__(256)
void mma_gemm_kernel(const float* __restrict__ x, float* __restrict__ out) {
    constexpr int NF = (MODE == 2) ? DIM : FDIM;
    constexpr int KF = (MODE == 2) ? FDIM : DIM;
    constexpr int NC = KF / 32;
    constexpr size_t SLICE = (size_t)MODE * (WSZ / 2);

    extern __shared__ char smem[];
    __shared__ int   s_rows[128];
    __shared__ float s_w[128];

    const int tid = threadIdx.x;
    const int lane = tid & 31, wid = tid >> 5;
    const int wm = wid >> 2, wn = wid & 3;

    const int e  = blockIdx.y / MTILES;
    const int mt = blockIdx.y % MTILES;
    int segBeg = g_off[e], segEnd = g_off[e + 1];
    if (segBeg < 0) segBeg = 0;
    if (segEnd > NSLOT) segEnd = NSLOT;
    const int m0 = segBeg + mt * 128;
    if (m0 >= segEnd) return;
    const int mrem = segEnd - m0;
    const int n0 = blockIdx.x * 128;

    if (tid < 128) {
        const int idx = m0 + tid;
        int r = -1; float w = 0.f;
        if (idx < segEnd) {
            r = g_perm[idx];
            if (r < 0) r = 0;
            if (r >= T_TOK) r = T_TOK - 1;
            w = g_wt[idx];
        }
        s_rows[tid] = r; s_w[tid] = w;
    }
    __syncthreads();

    const uint32_t sb = smem_u32(smem);
    const int arow = tid >> 1, acg = tid & 1;   // loader: row 0..127, half 0..1 (16 floats / 32B bf16)

    // staging regs
    uint32_t hA[8], lA[8];
    uint4 hB[2], lB[2];

    auto GLD = [&](int c) {
        const int k0 = c * 32;
        // ---- A ----
        if (MODE != 2) {
            const int rsrc = s_rows[arow];
            if (rsrc >= 0) {
                const float4* p = (const float4*)(x + (size_t)rsrc * DIM + k0 + acg * 16);
                #pragma unroll
                for (int j = 0; j < 4; j++) { const float4 v = p[j]; split4(v, hA + 2 * j, lA + 2 * j); }
            } else {
                #pragma unroll
                for (int j = 0; j < 8; j++) { hA[j] = 0u; lA[j] = 0u; }
            }
        } else {
            if (arow < mrem) {
                const size_t slot = (size_t)(m0 + arow);
                const float4* pg = (const float4*)(g_G + slot * FDIM + k0 + acg * 16);
                const float4* pu = (const float4*)(g_U + slot * FDIM + k0 + acg * 16);
                const float w = s_w[arow];
                #pragma unroll
                for (int j = 0; j < 4; j++) {
                    const float4 g = pg[j];
                    const float4 u = pu[j];
                    float4 h;
                    h.x = w * u.x * (g.x / (1.f + __expf(-g.x)));
                    h.y = w * u.y * (g.y / (1.f + __expf(-g.y)));
                    h.z = w * u.z * (g.z / (1.f + __expf(-g.z)));
                    h.w = w * u.w * (g.w / (1.f + __expf(-g.w)));
                    split4(h, hA + 2 * j, lA + 2 * j);
                }
            } else {
                #pragma unroll
                for (int j = 0; j < 8; j++) { hA[j] = 0u; lA[j] = 0u; }
            }
        }
        // ---- B ---- (pre-split bf16; row = n, K-contiguous)
        {
            const size_t boff = SLICE + ((((size_t)e * NF + n0 + arow) * KF + k0) >> 1) + acg * 8;
            const uint4* ph = (const uint4*)(g_Whi + boff);
            const uint4* pl = (const uint4*)(g_Wlo + boff);
            hB[0] = ph[0]; hB[1] = ph[1];
            lB[0] = pl[0]; lB[1] = pl[1];
        }
    };

    auto STS = [&](int c) {
        const uint32_t st = sb + (uint32_t)(c & 1) * 40960u;
        const uint32_t ao = (uint32_t)(arow * 80 + acg * 32);
        STS128(st + ao,              hA[0], hA[1], hA[2], hA[3]);
        STS128(st + ao + 16,         hA[4], hA[5], hA[6], hA[7]);
        STS128(st + 10240 + ao,      lA[0], lA[1], lA[2], lA[3]);
        STS128(st + 10240 + ao + 16, lA[4], lA[5], lA[6], lA[7]);
        STS128(st + 20480 + ao,      hB[0].x, hB[0].y, hB[0].z, hB[0].w);
        STS128(st + 20480 + ao + 16, hB[1].x, hB[1].y, hB[1].z, hB[1].w);
        STS128(st + 30720 + ao,      lB[0].x, lB[0].y, lB[0].z, lB[0].w);
        STS128(st + 30720 + ao + 16, lB[1].x, lB[1].y, lB[1].z, lB[1].w);
    };

    float acc[4][4][4];
    #pragma unroll
    for (int i = 0; i < 4; i++)
        #pragma unroll
        for (int j = 0; j < 4; j++)
            #pragma unroll
            for (int k = 0; k < 4; k++) acc[i][j][k] = 0.f;

    const int lr = lane & 15, lh = lane >> 4;
    const uint32_t aoffw = (uint32_t)((wm * 64 + lr) * 80 + lh * 16);
    const uint32_t boffw = (uint32_t)(20480 + (wn * 32 + lr) * 80 + lh * 16);

    GLD(0); STS(0); __syncthreads();
    for (int c = 0; c < NC; c++) {
        if (c + 1 < NC) GLD(c + 1);
        const uint32_t st = sb + (uint32_t)(c & 1) * 40960u;
        #pragma unroll
        for (int ks = 0; ks < 2; ks++) {
            uint32_t ah[4][4], al[4][4], bh[2][4], bl[2][4];
            #pragma unroll
            for (int mi = 0; mi < 4; mi++) {
                ldm4(ah[mi], st + aoffw + mi * 16 * 80 + ks * 32);
                ldm4(al[mi], st + 10240 + aoffw + mi * 16 * 80 + ks * 32);
            }
            #pragma unroll
            for (int ni = 0; ni < 2; ni++) {
                ldm4(bh[ni], st + boffw + ni * 16 * 80 + ks * 32);
                ldm4(bl[ni], st + 10240 + boffw + ni * 16 * 80 + ks * 32);
            }
            #pragma unroll
            for (int mi = 0; mi < 4; mi++)
                #pragma unroll
                for (int ni = 0; ni < 2; ni++)
                    #pragma unroll
                    for (int j = 0; j < 2; j++) {
                        float* d = acc[mi][ni * 2 + j];
                        mma16816(d, ah[mi], bh[ni][j], bh[ni][j + 2]);  // Ahi*Bhi
                        mma16816(d, ah[mi], bl[ni][j], bl[ni][j + 2]);  // Ahi*Blo
                        mma16816(d, al[mi], bh[ni][j], bh[ni][j + 2]);  // Alo*Bhi
                    }
        }
        if (c + 1 < NC) STS(c + 1);
        __syncthreads();
    }

    // ---- epilogue ----
    const int t4 = lane >> 2, t2 = (lane & 3) * 2;
    #pragma unroll
    for (int mi = 0; mi < 4; mi++) {
        #pragma unroll
        for (int half = 0; half < 2; half++) {
            const int row = wm * 64 + mi * 16 + t4 + half * 8;
            if (row < mrem) {
                if (MODE != 2) {
                    float* C = (MODE == 0) ? g_G : g_U;
                    float* crow = C + (size_t)(m0 + row) * NF + n0 + wn * 32;
                    #pragma unroll
                    for (int nj = 0; nj < 4; nj++) {
                        float2 v;
                        v.x = acc[mi][nj][half * 2 + 0];
                        v.y = acc[mi][nj][half * 2 + 1];
                        *(float2*)(crow + nj * 8 + t2) = v;
                    }
                } else {
                    int tok = g_perm[m0 + row];
                    if (tok < 0) tok = 0;
                    if (tok >= T_TOK) tok = T_TOK - 1;
                    float* orow = out + (size_t)tok * DIM + n0 + wn * 32;
                    #pragma unroll
                    for (int nj = 0; nj < 4; nj++) {
                        atomicAdd(orow + nj * 8 + t2,     acc[mi][nj][half * 2 + 0]);
                        atomicAdd(orow + nj * 8 + t2 + 1, acc[mi][nj][half * 2 + 1]);
                    }
                }
            }
        }
    }
}

// ---------------- launch ----------------
extern "C" void kernel_launch(void* const* d_in, const int* in_sizes, int n_in,
                              void* d_out, int out_size) {
    long long smax = -1;
    for (int i = 0; i < n_in; i++)
        if ((long long)in_sizes[i] > smax) smax = in_sizes[i];
    const float* w3[3] = {0, 0, 0};
    int wpos[3] = {-1, -1, -1};
    int nw = 0, ih = -1, irt = -1;
    for (int i = 0; i < n_in; i++)
        if ((long long)in_sizes[i] == smax && nw < 3) { w3[nw] = (const float*)d_in[i]; wpos[nw] = i; nw++; }
    long long best_h = -1;
    for (int i = 0; i < n_in; i++) {
        if (i == wpos[0] || i == wpos[1] || i == wpos[2]) continue;
        if ((long long)in_sizes[i] > best_h) { best_h = in_sizes[i]; ih = i; }
    }
    long long best_r = (long long)1 << 62;
    for (int i = 0; i < n_in; i++) {
        if (i == wpos[0] || i == wpos[1] || i == wpos[2] || i == ih) continue;
        if ((long long)in_sizes[i] < best_r) { best_r = in_sizes[i]; irt = i; }
    }
    const float* x  = (ih  >= 0) ? (const float*)d_in[ih]  : (const float*)d_in[0];
    const float* rw = (irt >= 0) ? (const float*)d_in[irt] : (const float*)d_in[1];
    const float *gw, *uw, *dw;
    if (nw == 3) {
        if (ih == 2) { dw = w3[0]; gw = w3[1]; uw = w3[2]; }
        else         { gw = w3[0]; uw = w3[1]; dw = w3[2]; }
    } else {
        x  = (const float*)d_in[0]; rw = (const float*)d_in[1];
        gw = (const float*)d_in[2]; uw = (const float*)d_in[3]; dw = (const float*)d_in[4];
    }
    float* out = (float*)d_out;

    const int need = T_TOK * DIM + T_TOK * NEXP;
    const int write_logits = (out_size >= need) ? 1 : 0;
    float* logits = out + (size_t)T_TOK * DIM;

    cudaFuncSetAttribute(mma_gemm_kernel<0>, cudaFuncAttributeMaxDynamicSharedMemorySize, MM_SMEM);
    cudaFuncSetAttribute(mma_gemm_kernel<1>, cudaFuncAttributeMaxDynamicSharedMemorySize, MM_SMEM);
    cudaFuncSetAttribute(mma_gemm_kernel<2>, cudaFuncAttributeMaxDynamicSharedMemorySize, MM_SMEM);

    zero_out_kernel<<<(T_TOK * DIM / 4 + 255) / 256, 256>>>(out);
    conv_kernel<<<4096, 256>>>((const float4*)gw, 0);
    conv_kernel<<<4096, 256>>>((const float4*)uw, 1);
    conv_kernel<<<4096, 256>>>((const float4*)dw, 2);
    router_kernel<<<T_TOK, 256>>>(x, rw, logits, write_logits);
    route_build_kernel<<<1, 512>>>();

    mma_gemm_kernel<0><<<dim3(FDIM / 128, NEXP * MTILES), 256, MM_SMEM>>>(x, out);
    mma_gemm_kernel<1><<<dim3(FDIM / 128, NEXP * MTILES), 256, MM_SMEM>>>(x, out);
    mma_gemm_kernel<2><<<dim3(DIM / 128, NEXP * MTILES), 256, MM_SMEM>>>(x, out);
}

// round 10
// speedup vs baseline: 5.3897x; 1.3231x over previous
#include <cuda_runtime.h>
#include <cuda_bf16.h>
#include <math.h>
#include <stdint.h>

#define T_TOK 4096
#define DIM   2048
#define NEXP  16
#define FDIM  768
#define NSLOT (T_TOK * 2)
#define MTILES 64
#define WSZ ((size_t)NEXP * FDIM * DIM)

// ---------------- device scratch; NEVER passed as kernel args (ATS host-shadow hazard) ----------------
__device__ __align__(16) int      g_off[NEXP + 1];
__device__ __align__(16) int      g_tok_e[NSLOT];
__device__ __align__(16) float    g_tok_w[NSLOT];
__device__ __align__(16) int      g_perm[NSLOT];
__device__ __align__(16) float    g_wt[NSLOT];
__device__ __align__(16) float    g_G[(size_t)NSLOT * FDIM];      // raw gate proj (fp32)
__device__ __align__(16) float    g_U[(size_t)NSLOT * FDIM];      // raw up proj  (fp32)
__device__ __align__(16) uint32_t g_Whi[3 * WSZ / 2];             // bf16x2 hi: [gate|up|down]
__device__ __align__(16) uint32_t g_Wlo[3 * WSZ / 2];             // bf16x2 lo
__device__ __align__(16) uint32_t g_Xhi[(size_t)T_TOK * DIM / 2]; // x split
__device__ __align__(16) uint32_t g_Xlo[(size_t)T_TOK * DIM / 2];
__device__ __align__(16) uint32_t g_Hhi[(size_t)NSLOT * FDIM / 2];// h split
__device__ __align__(16) uint32_t g_Hlo[(size_t)NSLOT * FDIM / 2];

// ---------------- helpers ----------------
__device__ __forceinline__ uint32_t smem_u32(const void* p) {
    uint32_t a;
    asm("{ .reg .u64 t; cvta.to.shared.u64 t, %1; cvt.u32.u64 %0, t; }" : "=r"(a) : "l"(p));
    return a;
}
#define STS128(addr, r0, r1, r2, r3) \
    asm volatile("st.shared.v4.b32 [%0], {%1,%2,%3,%4};" :: "r"(addr), "r"(r0), "r"(r1), "r"(r2), "r"(r3) : "memory")

__device__ __forceinline__ void ldm4(uint32_t* r, uint32_t addr) {
    asm volatile("ldmatrix.sync.aligned.m8n8.x4.shared.b16 {%0,%1,%2,%3}, [%4];"
        : "=r"(r[0]), "=r"(r[1]), "=r"(r[2]), "=r"(r[3]) : "r"(addr));
}
__device__ __forceinline__ void mma16816(float* d, const uint32_t* a, uint32_t b0, uint32_t b1) {
    asm volatile(
        "mma.sync.aligned.m16n8k16.row.col.f32.bf16.bf16.f32 "
        "{%0,%1,%2,%3}, {%4,%5,%6,%7}, {%8,%9}, {%0,%1,%2,%3};"
        : "+f"(d[0]), "+f"(d[1]), "+f"(d[2]), "+f"(d[3])
        : "r"(a[0]), "r"(a[1]), "r"(a[2]), "r"(a[3]), "r"(b0), "r"(b1));
}
__device__ __forceinline__ void split4(float4 v, uint32_t* hi, uint32_t* lo) {
    __nv_bfloat162 h0 = __floats2bfloat162_rn(v.x, v.y);
    __nv_bfloat162 h1 = __floats2bfloat162_rn(v.z, v.w);
    float2 f0 = __bfloat1622float2(h0);
    float2 f1 = __bfloat1622float2(h1);
    __nv_bfloat162 l0 = __floats2bfloat162_rn(v.x - f0.x, v.y - f0.y);
    __nv_bfloat162 l1 = __floats2bfloat162_rn(v.z - f1.x, v.w - f1.y);
    hi[0] = *(uint32_t*)&h0; hi[1] = *(uint32_t*)&h1;
    lo[0] = *(uint32_t*)&l0; lo[1] = *(uint32_t*)&l1;
}

// ---------------- zero output ----------------
__global__ void zero_out_kernel(float* __restrict__ out) {
    const size_t i = (size_t)blockIdx.x * blockDim.x + threadIdx.x;
    if (i < (size_t)T_TOK * DIM / 4)
        ((float4*)out)[i] = make_float4(0.f, 0.f, 0.f, 0.f);
}

// ---------------- weight pre-split (slice: 0 gate, 1 up, 2 down) ----------------
__global__ void conv_kernel(const float4* __restrict__ src, int slice) {
    const size_t base = (size_t)slice * (WSZ / 2);
    const size_t n4 = WSZ / 4;
    for (size_t i = (size_t)blockIdx.x * blockDim.x + threadIdx.x; i < n4;
         i += (size_t)gridDim.x * blockDim.x) {
        const float4 v = src[i];
        uint32_t hi[2], lo[2];
        split4(v, hi, lo);
        uint2 hu, lu; hu.x = hi[0]; hu.y = hi[1]; lu.x = lo[0]; lu.y = lo[1];
        *(uint2*)&g_Whi[base + 2 * i] = hu;
        *(uint2*)&g_Wlo[base + 2 * i] = lu;
    }
}

// ---------------- x pre-split ----------------
__global__ void xsplit_kernel(const float4* __restrict__ src) {
    const size_t n4 = (size_t)T_TOK * DIM / 4;
    const size_t i = (size_t)blockIdx.x * blockDim.x + threadIdx.x;
    if (i >= n4) return;
    const float4 v = src[i];
    uint32_t hi[2], lo[2];
    split4(v, hi, lo);
    uint2 hu, lu; hu.x = hi[0]; hu.y = hi[1]; lu.x = lo[0]; lu.y = lo[1];
    *(uint2*)&g_Xhi[2 * i] = hu;
    *(uint2*)&g_Xlo[2 * i] = lu;
}

// ---------------- h = wt * silu(G) * U -> bf16 hi/lo split ----------------
__global__ void swiglu_split_kernel() {
    const size_t n4 = (size_t)NSLOT * FDIM / 4;
    const size_t i = (size_t)blockIdx.x * blockDim.x + threadIdx.x;
    if (i >= n4) return;
    const int slot = (int)(i / (FDIM / 4));
    const float w = g_wt[slot];
    const float4 g = ((const float4*)g_G)[i];
    const float4 u = ((const float4*)g_U)[i];
    float4 h;
    h.x = w * u.x * (g.x / (1.f + __expf(-g.x)));
    h.y = w * u.y * (g.y / (1.f + __expf(-g.y)));
    h.z = w * u.z * (g.z / (1.f + __expf(-g.z)));
    h.w = w * u.w * (g.w / (1.f + __expf(-g.w)));
    uint32_t hi[2], lo[2];
    split4(h, hi, lo);
    uint2 hu, lu; hu.x = hi[0]; hu.y = hi[1]; lu.x = lo[0]; lu.y = lo[1];
    *(uint2*)&g_Hhi[2 * i] = hu;
    *(uint2*)&g_Hlo[2 * i] = lu;
}

// ---------------- router (proven) ----------------
__global__ __launch_bounds__(256)
void router_kernel(const float* __restrict__ x,
                   const float* __restrict__ rw,
                   float* __restrict__ logits_out,
                   int write_logits) {
    __shared__ float xs[DIM];
    __shared__ float lg[NEXP];
    const int t = blockIdx.x;
    const int tid = threadIdx.x;
    const int warp = tid >> 5, lane = tid & 31;

    const float4* xg = (const float4*)(x + (size_t)t * DIM);
    for (int i = tid; i < DIM / 4; i += 256) ((float4*)xs)[i] = xg[i];
    __syncthreads();
    {
        const float4* w0 = (const float4*)(rw + (size_t)(warp * 2) * DIM);
        const float4* w1 = (const float4*)(rw + (size_t)(warp * 2 + 1) * DIM);
        float a0 = 0.f, a1 = 0.f;
        for (int i = lane; i < DIM / 4; i += 32) {
            const float4 xv = ((const float4*)xs)[i];
            const float4 va = w0[i];
            const float4 vb = w1[i];
            a0 += xv.x * va.x + xv.y * va.y + xv.z * va.z + xv.w * va.w;
            a1 += xv.x * vb.x + xv.y * vb.y + xv.z * vb.z + xv.w * vb.w;
        }
        #pragma unroll
        for (int o = 16; o > 0; o >>= 1) {
            a0 += __shfl_xor_sync(0xffffffffu, a0, o);
            a1 += __shfl_xor_sync(0xffffffffu, a1, o);
        }
        if (lane == 0) { lg[warp * 2] = a0; lg[warp * 2 + 1] = a1; }
    }
    __syncthreads();
    if (write_logits && tid < NEXP)
        logits_out[(size_t)t * NEXP + tid] = lg[tid];
    if (tid == 0) {
        int i0 = 0;
        #pragma unroll
        for (int i = 1; i < NEXP; i++)
            if (lg[i] > lg[i0]) i0 = i;
        int i1 = (i0 == 0) ? 1 : 0;
        #pragma unroll
        for (int i = 0; i < NEXP; i++) {
            if (i == i0) continue;
            if (lg[i] > lg[i1]) i1 = i;
        }
        const float e1 = __expf(lg[i1] - lg[i0]);
        const float s = 1.0f + e1;
        g_tok_e[2 * t + 0] = i0; g_tok_w[2 * t + 0] = 1.0f / s;
        g_tok_e[2 * t + 1] = i1; g_tok_w[2 * t + 1] = e1 / s;
    }
}

// ---------------- compaction (proven) ----------------
__global__ void route_build_kernel() {
    __shared__ int s_cnt[NEXP];
    __shared__ int s_off[NEXP + 1];
    const int tid = threadIdx.x;
    if (tid < NEXP) s_cnt[tid] = 0;
    __syncthreads();
    for (int i = tid; i < NSLOT; i += 512)
        atomicAdd(&s_cnt[g_tok_e[i] & (NEXP - 1)], 1);
    __syncthreads();
    if (tid == 0) {
        int off = 0;
        #pragma unroll
        for (int e = 0; e < NEXP; e++) { s_off[e] = off; g_off[e] = off; off += s_cnt[e]; }
        s_off[NEXP] = off; g_off[NEXP] = off;
    }
    __syncthreads();
    const int warp = tid >> 5, lane = tid & 31;
    int base = s_off[warp];
    for (int i0 = 0; i0 < NSLOT; i0 += 32) {
        const int i = i0 + lane;
        const bool m = ((g_tok_e[i] & (NEXP - 1)) == warp);
        const unsigned mask = __ballot_sync(0xffffffffu, m);
        if (m) {
            const int pos = base + __popc(mask & ((1u << lane) - 1u));
            if (pos < NSLOT) {
                g_perm[pos] = i >> 1;
                g_wt[pos]   = g_tok_w[i];
            }
        }
        base += __popc(mask);
    }
}

// ================= mma.sync grouped GEMM (all operands pre-split bf16) =================
// MODE 0: g_G = gather(Xsplit) @ gate^T   (K=2048, N=768)
// MODE 1: g_U = gather(Xsplit) @ up^T     (K=2048, N=768)
// MODE 2: out += Hsplit @ down^T, scatter-add (K=768, N=2048)
// Tile M=128 x N=128, K-chunk 32. Stage 40960 B: A_hi 0 | A_lo 10240 | B_hi 20480 | B_lo 30720 (80 B rows).
#define MM_SMEM (2 * 40960)

template <int MODE>
__global__ __launch_bounds__(256)
void mma_gemm_kernel(float* __restrict__ out) {
    constexpr int NF = (MODE == 2) ? DIM : FDIM;
    constexpr int KF = (MODE == 2) ? FDIM : DIM;
    constexpr int NC = KF / 32;
    constexpr size_t SLICE = (size_t)MODE * (WSZ / 2);

    extern __shared__ char smem[];
    __shared__ int s_rows[128];

    const int tid = threadIdx.x;
    const int lane = tid & 31, wid = tid >> 5;
    const int wm = wid >> 2, wn = wid & 3;

    const int e  = blockIdx.y / MTILES;
    const int mt = blockIdx.y % MTILES;
    int segBeg = g_off[e], segEnd = g_off[e + 1];
    if (segBeg < 0) segBeg = 0;
    if (segEnd > NSLOT) segEnd = NSLOT;
    const int m0 = segBeg + mt * 128;
    if (m0 >= segEnd) return;
    const int mrem = segEnd - m0;
    const int n0 = blockIdx.x * 128;

    if (tid < 128) {
        const int idx = m0 + tid;
        int r = -1;
        if (idx < segEnd) {
            if (MODE == 2) r = idx;                     // slot-indexed H
            else {
                r = g_perm[idx];
                if (r < 0) r = 0;
                if (r >= T_TOK) r = T_TOK - 1;
            }
        }
        s_rows[tid] = r;
    }
    __syncthreads();

    const uint32_t sb = smem_u32(smem);
    const int arow = tid >> 1, acg = tid & 1;

    const uint32_t* Ahi = (MODE == 2) ? g_Hhi : g_Xhi;
    const uint32_t* Alo = (MODE == 2) ? g_Hlo : g_Xlo;

    uint4 stA[4], stB[4];   // [hi0, hi1, lo0, lo1]

    auto GLD = [&](int c) {
        const int k0 = c * 32;
        const int rsrc = s_rows[arow];
        if (rsrc >= 0) {
            const size_t ao = (((size_t)rsrc * KF + k0) >> 1) + acg * 8;
            const uint4* ph = (const uint4*)(Ahi + ao);
            const uint4* pl = (const uint4*)(Alo + ao);
            stA[0] = ph[0]; stA[1] = ph[1];
            stA[2] = pl[0]; stA[3] = pl[1];
        } else {
            const uint4 z = make_uint4(0u, 0u, 0u, 0u);
            stA[0] = z; stA[1] = z; stA[2] = z; stA[3] = z;
        }
        const size_t bo = SLICE + ((((size_t)e * NF + n0 + arow) * KF + k0) >> 1) + acg * 8;
        const uint4* ph = (const uint4*)(g_Whi + bo);
        const uint4* pl = (const uint4*)(g_Wlo + bo);
        stB[0] = ph[0]; stB[1] = ph[1];
        stB[2] = pl[0]; stB[3] = pl[1];
    };

    auto STS = [&](int c) {
        const uint32_t st = sb + (uint32_t)(c & 1) * 40960u;
        const uint32_t ao = (uint32_t)(arow * 80 + acg * 32);
        STS128(st + ao,              stA[0].x, stA[0].y, stA[0].z, stA[0].w);
        STS128(st + ao + 16,         stA[1].x, stA[1].y, stA[1].z, stA[1].w);
        STS128(st + 10240 + ao,      stA[2].x, stA[2].y, stA[2].z, stA[2].w);
        STS128(st + 10240 + ao + 16, stA[3].x, stA[3].y, stA[3].z, stA[3].w);
        STS128(st + 20480 + ao,      stB[0].x, stB[0].y, stB[0].z, stB[0].w);
        STS128(st + 20480 + ao + 16, stB[1].x, stB[1].y, stB[1].z, stB[1].w);
        STS128(st + 30720 + ao,      stB[2].x, stB[2].y, stB[2].z, stB[2].w);
        STS128(st + 30720 + ao + 16, stB[3].x, stB[3].y, stB[3].z, stB[3].w);
    };

    float acc[4][4][4];
    #pragma unroll
    for (int i = 0; i < 4; i++)
        #pragma unroll
        for (int j = 0; j < 4; j++)
            #pragma unroll
            for (int k = 0; k < 4; k++) acc[i][j][k] = 0.f;

    const int lr = lane & 15, lh = lane >> 4;
    const uint32_t aoffw = (uint32_t)((wm * 64 + lr) * 80 + lh * 16);
    const uint32_t boffw = (uint32_t)(20480 + (wn * 32 + lr) * 80 + lh * 16);

    GLD(0); STS(0); __syncthreads();
    for (int c = 0; c < NC; c++) {
        if (c + 1 < NC) GLD(c + 1);
        const uint32_t st = sb + (uint32_t)(c & 1) * 40960u;
        #pragma unroll
        for (int ks = 0; ks < 2; ks++) {
            uint32_t ah[4][4], al[4][4], bh[2][4], bl[2][4];
            #pragma unroll
            for (int mi = 0; mi < 4; mi++) {
                ldm4(ah[mi], st + aoffw + mi * 16 * 80 + ks * 32);
                ldm4(al[mi], st + 10240 + aoffw + mi * 16 * 80 + ks * 32);
            }
            #pragma unroll
            for (int ni = 0; ni < 2; ni++) {
                ldm4(bh[ni], st + boffw + ni * 16 * 80 + ks * 32);
                ldm4(bl[ni], st + 10240 + boffw + ni * 16 * 80 + ks * 32);
            }
            // term-major ordering: 16 independent accumulators between reuse -> no RAW chains
            #pragma unroll
            for (int mi = 0; mi < 4; mi++)
                #pragma unroll
                for (int ni = 0; ni < 2; ni++)
                    #pragma unroll
                    for (int j = 0; j < 2; j++)
                        mma16816(acc[mi][ni * 2 + j], ah[mi], bh[ni][j], bh[ni][j + 2]);
            #pragma unroll
            for (int mi = 0; mi < 4; mi++)
                #pragma unroll
                for (int ni = 0; ni < 2; ni++)
                    #pragma unroll
                    for (int j = 0; j < 2; j++)
                        mma16816(acc[mi][ni * 2 + j], ah[mi], bl[ni][j], bl[ni][j + 2]);
            #pragma unroll
            for (int mi = 0; mi < 4; mi++)
                #pragma unroll
                for (int ni = 0; ni < 2; ni++)
                    #pragma unroll
                    for (int j = 0; j < 2; j++)
                        mma16816(acc[mi][ni * 2 + j], al[mi], bh[ni][j], bh[ni][j + 2]);
        }
        if (c + 1 < NC) STS(c + 1);
        __syncthreads();
    }

    // ---- epilogue (proven R9 mapping) ----
    const int t4 = lane >> 2, t2 = (lane & 3) * 2;
    #pragma unroll
    for (int mi = 0; mi < 4; mi++) {
        #pragma unroll
        for (int half = 0; half < 2; half++) {
            const int row = wm * 64 + mi * 16 + t4 + half * 8;
            if (row < mrem) {
                if (MODE != 2) {
                    float* C = (MODE == 0) ? g_G : g_U;
                    float* crow = C + (size_t)(m0 + row) * NF + n0 + wn * 32;
                    #pragma unroll
                    for (int nj = 0; nj < 4; nj++) {
                        float2 v;
                        v.x = acc[mi][nj][half * 2 + 0];
                        v.y = acc[mi][nj][half * 2 + 1];
                        *(float2*)(crow + nj * 8 + t2) = v;
                    }
                } else {
                    int tok = g_perm[m0 + row];
                    if (tok < 0) tok = 0;
                    if (tok >= T_TOK) tok = T_TOK - 1;
                    float* orow = out + (size_t)tok * DIM + n0 + wn * 32;
                    #pragma unroll
                    for (int nj = 0; nj < 4; nj++) {
                        atomicAdd(orow + nj * 8 + t2,     acc[mi][nj][half * 2 + 0]);
                        atomicAdd(orow + nj * 8 + t2 + 1, acc[mi][nj][half * 2 + 1]);
                    }
                }
            }
        }
    }
}

// ---------------- launch ----------------
extern "C" void kernel_launch(void* const* d_in, const int* in_sizes, int n_in,
                              void* d_out, int out_size) {
    long long smax = -1;
    for (int i = 0; i < n_in; i++)
        if ((long long)in_sizes[i] > smax) smax = in_sizes[i];
    const float* w3[3] = {0, 0, 0};
    int wpos[3] = {-1, -1, -1};
    int nw = 0, ih = -1, irt = -1;
    for (int i = 0; i < n_in; i++)
        if ((long long)in_sizes[i] == smax && nw < 3) { w3[nw] = (const float*)d_in[i]; wpos[nw] = i; nw++; }
    long long best_h = -1;
    for (int i = 0; i < n_in; i++) {
        if (i == wpos[0] || i == wpos[1] || i == wpos[2]) continue;
        if ((long long)in_sizes[i] > best_h) { best_h = in_sizes[i]; ih = i; }
    }
    long long best_r = (long long)1 << 62;
    for (int i = 0; i < n_in; i++) {
        if (i == wpos[0] || i == wpos[1] || i == wpos[2] || i == ih) continue;
        if ((long long)in_sizes[i] < best_r) { best_r = in_sizes[i]; irt = i; }
    }
    const float* x  = (ih  >= 0) ? (const float*)d_in[ih]  : (const float*)d_in[0];
    const float* rw = (irt >= 0) ? (const float*)d_in[irt] : (const float*)d_in[1];
    const float *gw, *uw, *dw;
    if (nw == 3) {
        if (ih == 2) { dw = w3[0]; gw = w3[1]; uw = w3[2]; }
        else         { gw = w3[0]; uw = w3[1]; dw = w3[2]; }
    } else {
        x  = (const float*)d_in[0]; rw = (const float*)d_in[1];
        gw = (const float*)d_in[2]; uw = (const float*)d_in[3]; dw = (const float*)d_in[4];
    }
    float* out = (float*)d_out;

    const int need = T_TOK * DIM + T_TOK * NEXP;
    const int write_logits = (out_size >= need) ? 1 : 0;
    float* logits = out + (size_t)T_TOK * DIM;

    cudaFuncSetAttribute(mma_gemm_kernel<0>, cudaFuncAttributeMaxDynamicSharedMemorySize, MM_SMEM);
    cudaFuncSetAttribute(mma_gemm_kernel<1>, cudaFuncAttributeMaxDynamicSharedMemorySize, MM_SMEM);
    cudaFuncSetAttribute(mma_gemm_kernel<2>, cudaFuncAttributeMaxDynamicSharedMemorySize, MM_SMEM);

    zero_out_kernel<<<(T_TOK * DIM / 4 + 255) / 256, 256>>>(out);
    conv_kernel<<<4096, 256>>>((const float4*)gw, 0);
    conv_kernel<<<4096, 256>>>((const float4*)uw, 1);
    conv_kernel<<<4096, 256>>>((const float4*)dw, 2);
    xsplit_kernel<<<(T_TOK * DIM / 4 + 255) / 256, 256>>>((const float4*)x);
    router_kernel<<<T_TOK, 256>>>(x, rw, logits, write_logits);
    route_build_kernel<<<1, 512>>>();

    mma_gemm_kernel<0><<<dim3(FDIM / 128, NEXP * MTILES), 256, MM_SMEM>>>(out);
    mma_gemm_kernel<1><<<dim3(FDIM / 128, NEXP * MTILES), 256, MM_SMEM>>>(out);
    swiglu_split_kernel<<<(NSLOT * FDIM / 4 + 255) / 256, 256>>>();
    mma_gemm_kernel<2><<<dim3(DIM / 128, NEXP * MTILES), 256, MM_SMEM>>>(out);
}

// round 11
// speedup vs baseline: 5.5482x; 1.0294x over previous
#include <cuda_runtime.h>
#include <cuda_bf16.h>
#include <math.h>
#include <stdint.h>

#define T_TOK 4096
#define DIM   2048
#define NEXP  16
#define FDIM  768
#define NSLOT (T_TOK * 2)
#define MTILES 64
#define WSZ ((size_t)NEXP * FDIM * DIM)

// ---------------- device scratch; NEVER passed as kernel args (ATS host-shadow hazard) ----------------
__device__ __align__(16) int      g_off[NEXP + 1];
__device__ __align__(16) int      g_tok_e[NSLOT];
__device__ __align__(16) float    g_tok_w[NSLOT];
__device__ __align__(16) int      g_perm[NSLOT];
__device__ __align__(16) float    g_wt[NSLOT];
__device__ __align__(16) uint32_t g_Whi[3 * WSZ / 2];             // bf16x2 hi: [gate|up|down]
__device__ __align__(16) uint32_t g_Wlo[3 * WSZ / 2];             // bf16x2 lo
__device__ __align__(16) uint32_t g_Xhi[(size_t)T_TOK * DIM / 2]; // x split
__device__ __align__(16) uint32_t g_Xlo[(size_t)T_TOK * DIM / 2];
__device__ __align__(16) uint32_t g_Hhi[(size_t)NSLOT * FDIM / 2];// h split
__device__ __align__(16) uint32_t g_Hlo[(size_t)NSLOT * FDIM / 2];

// ---------------- helpers ----------------
__device__ __forceinline__ uint32_t smem_u32(const void* p) {
    uint32_t a;
    asm("{ .reg .u64 t; cvta.to.shared.u64 t, %1; cvt.u32.u64 %0, t; }" : "=r"(a) : "l"(p));
    return a;
}
#define CP16(dst, src, sz) \
    asm volatile("cp.async.cg.shared.global [%0], [%1], 16, %2;" \
        :: "r"(dst), "l"(src), "r"(sz) : "memory")
#define CP_COMMIT() asm volatile("cp.async.commit_group;" ::: "memory")
#define CP_WAIT1()  asm volatile("cp.async.wait_group 1;" ::: "memory")
#define CP_WAIT0()  asm volatile("cp.async.wait_group 0;" ::: "memory")

__device__ __forceinline__ void ldm4(uint32_t* r, uint32_t addr) {
    asm volatile("ldmatrix.sync.aligned.m8n8.x4.shared.b16 {%0,%1,%2,%3}, [%4];"
        : "=r"(r[0]), "=r"(r[1]), "=r"(r[2]), "=r"(r[3]) : "r"(addr));
}
__device__ __forceinline__ void mma16816(float* d, const uint32_t* a, uint32_t b0, uint32_t b1) {
    asm volatile(
        "mma.sync.aligned.m16n8k16.row.col.f32.bf16.bf16.f32 "
        "{%0,%1,%2,%3}, {%4,%5,%6,%7}, {%8,%9}, {%0,%1,%2,%3};"
        : "+f"(d[0]), "+f"(d[1]), "+f"(d[2]), "+f"(d[3])
        : "r"(a[0]), "r"(a[1]), "r"(a[2]), "r"(a[3]), "r"(b0), "r"(b1));
}
__device__ __forceinline__ void split4(float4 v, uint32_t* hi, uint32_t* lo) {
    __nv_bfloat162 h0 = __floats2bfloat162_rn(v.x, v.y);
    __nv_bfloat162 h1 = __floats2bfloat162_rn(v.z, v.w);
    float2 f0 = __bfloat1622float2(h0);
    float2 f1 = __bfloat1622float2(h1);
    __nv_bfloat162 l0 = __floats2bfloat162_rn(v.x - f0.x, v.y - f0.y);
    __nv_bfloat162 l1 = __floats2bfloat162_rn(v.z - f1.x, v.w - f1.y);
    hi[0] = *(uint32_t*)&h0; hi[1] = *(uint32_t*)&h1;
    lo[0] = *(uint32_t*)&l0; lo[1] = *(uint32_t*)&l1;
}

// ---------------- zero output ----------------
__global__ void zero_out_kernel(float* __restrict__ out) {
    const size_t i = (size_t)blockIdx.x * blockDim.x + threadIdx.x;
    if (i < (size_t)T_TOK * DIM / 4)
        ((float4*)out)[i] = make_float4(0.f, 0.f, 0.f, 0.f);
}

// ---------------- all-weights pre-split in ONE launch (grid.y = slice) ----------------
__global__ void conv_all_kernel(const float4* __restrict__ gw,
                                const float4* __restrict__ uw,
                                const float4* __restrict__ dw) {
    const int slice = blockIdx.y;
    const float4* src = (slice == 0) ? gw : (slice == 1) ? uw : dw;
    const size_t base = (size_t)slice * (WSZ / 2);
    const size_t n4 = WSZ / 4;
    for (size_t i = (size_t)blockIdx.x * blockDim.x + threadIdx.x; i < n4;
         i += (size_t)gridDim.x * blockDim.x) {
        const float4 v = src[i];
        uint32_t hi[2], lo[2];
        split4(v, hi, lo);
        uint2 hu, lu; hu.x = hi[0]; hu.y = hi[1]; lu.x = lo[0]; lu.y = lo[1];
        *(uint2*)&g_Whi[base + 2 * i] = hu;
        *(uint2*)&g_Wlo[base + 2 * i] = lu;
    }
}

// ---------------- x pre-split ----------------
__global__ void xsplit_kernel(const float4* __restrict__ src) {
    const size_t n4 = (size_t)T_TOK * DIM / 4;
    const size_t i = (size_t)blockIdx.x * blockDim.x + threadIdx.x;
    if (i >= n4) return;
    const float4 v = src[i];
    uint32_t hi[2], lo[2];
    split4(v, hi, lo);
    uint2 hu, lu; hu.x = hi[0]; hu.y = hi[1]; lu.x = lo[0]; lu.y = lo[1];
    *(uint2*)&g_Xhi[2 * i] = hu;
    *(uint2*)&g_Xlo[2 * i] = lu;
}

// ---------------- router (proven) ----------------
__global__ __launch_bounds__(256)
void router_kernel(const float* __restrict__ x,
                   const float* __restrict__ rw,
                   float* __restrict__ logits_out,
                   int write_logits) {
    __shared__ float xs[DIM];
    __shared__ float lg[NEXP];
    const int t = blockIdx.x;
    const int tid = threadIdx.x;
    const int warp = tid >> 5, lane = tid & 31;

    const float4* xg = (const float4*)(x + (size_t)t * DIM);
    for (int i = tid; i < DIM / 4; i += 256) ((float4*)xs)[i] = xg[i];
    __syncthreads();
    {
        const float4* w0 = (const float4*)(rw + (size_t)(warp * 2) * DIM);
        const float4* w1 = (const float4*)(rw + (size_t)(warp * 2 + 1) * DIM);
        float a0 = 0.f, a1 = 0.f;
        for (int i = lane; i < DIM / 4; i += 32) {
            const float4 xv = ((const float4*)xs)[i];
            const float4 va = w0[i];
            const float4 vb = w1[i];
            a0 += xv.x * va.x + xv.y * va.y + xv.z * va.z + xv.w * va.w;
            a1 += xv.x * vb.x + xv.y * vb.y + xv.z * vb.z + xv.w * vb.w;
        }
        #pragma unroll
        for (int o = 16; o > 0; o >>= 1) {
            a0 += __shfl_xor_sync(0xffffffffu, a0, o);
            a1 += __shfl_xor_sync(0xffffffffu, a1, o);
        }
        if (lane == 0) { lg[warp * 2] = a0; lg[warp * 2 + 1] = a1; }
    }
    __syncthreads();
    if (write_logits && tid < NEXP)
        logits_out[(size_t)t * NEXP + tid] = lg[tid];
    if (tid == 0) {
        int i0 = 0;
        #pragma unroll
        for (int i = 1; i < NEXP; i++)
            if (lg[i] > lg[i0]) i0 = i;
        int i1 = (i0 == 0) ? 1 : 0;
        #pragma unroll
        for (int i = 0; i < NEXP; i++) {
            if (i == i0) continue;
            if (lg[i] > lg[i1]) i1 = i;
        }
        const float e1 = __expf(lg[i1] - lg[i0]);
        const float s = 1.0f + e1;
        g_tok_e[2 * t + 0] = i0; g_tok_w[2 * t + 0] = 1.0f / s;
        g_tok_e[2 * t + 1] = i1; g_tok_w[2 * t + 1] = e1 / s;
    }
}

// ---------------- compaction (proven) ----------------
__global__ void route_build_kernel() {
    __shared__ int s_cnt[NEXP];
    __shared__ int s_off[NEXP + 1];
    const int tid = threadIdx.x;
    if (tid < NEXP) s_cnt[tid] = 0;
    __syncthreads();
    for (int i = tid; i < NSLOT; i += 512)
        atomicAdd(&s_cnt[g_tok_e[i] & (NEXP - 1)], 1);
    __syncthreads();
    if (tid == 0) {
        int off = 0;
        #pragma unroll
        for (int e = 0; e < NEXP; e++) { s_off[e] = off; g_off[e] = off; off += s_cnt[e]; }
        s_off[NEXP] = off; g_off[NEXP] = off;
    }
    __syncthreads();
    const int warp = tid >> 5, lane = tid & 31;
    int base = s_off[warp];
    for (int i0 = 0; i0 < NSLOT; i0 += 32) {
        const int i = i0 + lane;
        const bool m = ((g_tok_e[i] & (NEXP - 1)) == warp);
        const unsigned mask = __ballot_sync(0xffffffffu, m);
        if (m) {
            const int pos = base + __popc(mask & ((1u << lane) - 1u));
            if (pos < NSLOT) {
                g_perm[pos] = i >> 1;
                g_wt[pos]   = g_tok_w[i];
            }
        }
        base += __popc(mask);
    }
}

// ================= fused gate+up GEMM with in-register SwiGLU epilogue =================
// Block tile M=128 x N=64(F) for BOTH gate and up. K=2048, chunk 32, 3-stage cp.async.
// Stage 40960 B: A_hi 0 | A_lo 10240 | Bg_hi 20480 | Bg_lo 25600 | Bu_hi 30720 | Bu_lo 35840
#define GU_SMEM (3 * 40960)
__global__ __launch_bounds__(256, 1)
void gu_kernel() {
    constexpr int NC = DIM / 32;
    extern __shared__ char smem[];
    __shared__ int   s_rows[128];
    __shared__ float s_w[128];

    const int tid = threadIdx.x;
    const int lane = tid & 31, wid = tid >> 5;
    const int wm = wid >> 1, wn = wid & 1;          // 4 x 2 warps; warp tile 32 x 32 (both mats)

    const int e  = blockIdx.y / MTILES;
    const int mt = blockIdx.y % MTILES;
    int segBeg = g_off[e], segEnd = g_off[e + 1];
    if (segBeg < 0) segBeg = 0;
    if (segEnd > NSLOT) segEnd = NSLOT;
    const int m0 = segBeg + mt * 128;
    if (m0 >= segEnd) return;
    const int mrem = segEnd - m0;
    const int n0 = blockIdx.x * 64;

    if (tid < 128) {
        const int idx = m0 + tid;
        int r = -1; float w = 0.f;
        if (idx < segEnd) {
            r = g_perm[idx];
            if (r < 0) r = 0;
            if (r >= T_TOK) r = T_TOK - 1;
            w = g_wt[idx];
        }
        s_rows[tid] = r; s_w[tid] = w;
    }
    __syncthreads();

    const uint32_t sb = smem_u32(smem);
    const int arow = tid >> 1, acg = tid & 1;

    auto ISSUE = [&](int c) {
        const uint32_t st = sb + (uint32_t)(c % 3) * 40960u;
        const int k0 = c * 32;
        {   // A: gathered x (split)
            const int r = s_rows[arow];
            const uint32_t sz = (r >= 0) ? 16u : 0u;
            const size_t ao = (((size_t)(r < 0 ? 0 : r) * DIM + k0) >> 1) + (size_t)acg * 8;
            const uint32_t da = st + (uint32_t)(arow * 80 + acg * 32);
            const uint64_t sh = __cvta_generic_to_global((const void*)(g_Xhi + ao));
            const uint64_t sl = __cvta_generic_to_global((const void*)(g_Xlo + ao));
            CP16(da,              sh,      sz);
            CP16(da + 16,         sh + 16, sz);
            CP16(da + 10240,      sl,      sz);
            CP16(da + 10240 + 16, sl + 16, sz);
        }
        {   // B: gate (rows 0-63) / up (rows 64-127)
            const int gu = arow >> 6;
            const int row = arow & 63;
            const size_t bo = (size_t)gu * (WSZ / 2)
                            + ((((size_t)e * FDIM + n0 + row) * DIM + k0) >> 1) + (size_t)acg * 8;
            const uint32_t db = st + 20480u + (uint32_t)(gu * 10240 + row * 80 + acg * 32);
            const uint64_t sh = __cvta_generic_to_global((const void*)(g_Whi + bo));
            const uint64_t sl = __cvta_generic_to_global((const void*)(g_Wlo + bo));
            CP16(db,             sh,      16u);
            CP16(db + 16,        sh + 16, 16u);
            CP16(db + 5120,      sl,      16u);
            CP16(db + 5120 + 16, sl + 16, 16u);
        }
        CP_COMMIT();
    };

    float acc[2][2][4][4];   // [gu][mi][n-frag][4]
    #pragma unroll
    for (int a = 0; a < 2; a++)
        #pragma unroll
        for (int b = 0; b < 2; b++)
            #pragma unroll
            for (int cN = 0; cN < 4; cN++)
                #pragma unroll
                for (int d = 0; d < 4; d++) acc[a][b][cN][d] = 0.f;

    const int lr = lane & 15, lh = lane >> 4;

    ISSUE(0); ISSUE(1);
    for (int c = 0; c < NC; c++) {
        if (c + 1 < NC) { CP_WAIT1(); } else { CP_WAIT0(); }
        __syncthreads();
        const uint32_t st = sb + (uint32_t)(c % 3) * 40960u;
        #pragma unroll
        for (int ks = 0; ks < 2; ks++) {
            uint32_t ah[2][4], al[2][4], bh[2][2][4], bl[2][2][4];
            #pragma unroll
            for (int mi = 0; mi < 2; mi++) {
                const uint32_t ao = st + (uint32_t)((wm * 32 + mi * 16 + lr) * 80 + ks * 32 + lh * 16);
                ldm4(ah[mi], ao);
                ldm4(al[mi], ao + 10240);
            }
            #pragma unroll
            for (int gu = 0; gu < 2; gu++)
                #pragma unroll
                for (int ni = 0; ni < 2; ni++) {
                    const uint32_t bo = st + 20480u + (uint32_t)(gu * 10240
                        + (wn * 32 + ni * 16 + lr) * 80 + ks * 32 + lh * 16);
                    ldm4(bh[gu][ni], bo);
                    ldm4(bl[gu][ni], bo + 5120);
                }
            // term-major: 16 independent accumulators between reuses
            #pragma unroll
            for (int gu = 0; gu < 2; gu++)
                #pragma unroll
                for (int mi = 0; mi < 2; mi++)
                    #pragma unroll
                    for (int ni = 0; ni < 2; ni++)
                        #pragma unroll
                        for (int j = 0; j < 2; j++)
                            mma16816(acc[gu][mi][ni * 2 + j], ah[mi], bh[gu][ni][j], bh[gu][ni][j + 2]);
            #pragma unroll
            for (int gu = 0; gu < 2; gu++)
                #pragma unroll
                for (int mi = 0; mi < 2; mi++)
                    #pragma unroll
                    for (int ni = 0; ni < 2; ni++)
                        #pragma unroll
                        for (int j = 0; j < 2; j++)
                            mma16816(acc[gu][mi][ni * 2 + j], ah[mi], bl[gu][ni][j], bl[gu][ni][j + 2]);
            #pragma unroll
            for (int gu = 0; gu < 2; gu++)
                #pragma unroll
                for (int mi = 0; mi < 2; mi++)
                    #pragma unroll
                    for (int ni = 0; ni < 2; ni++)
                        #pragma unroll
                        for (int j = 0; j < 2; j++)
                            mma16816(acc[gu][mi][ni * 2 + j], al[mi], bh[gu][ni][j], bh[gu][ni][j + 2]);
        }
        if (c + 2 < NC) ISSUE(c + 2);
        __syncthreads();
    }

    // ---- epilogue: h = wt * silu(g) * u -> split bf16 hi/lo -> g_Hhi/g_Hlo ----
    const int t4 = lane >> 2, l3 = lane & 3;
    #pragma unroll
    for (int mi = 0; mi < 2; mi++) {
        #pragma unroll
        for (int half = 0; half < 2; half++) {
            const int row = wm * 32 + mi * 16 + t4 + half * 8;
            if (row < mrem) {
                const float wt = s_w[row];
                const size_t base = (size_t)(m0 + row) * (FDIM / 2) + (size_t)((n0 + wn * 32) >> 1) + l3;
                #pragma unroll
                for (int nj = 0; nj < 4; nj++) {
                    const float gx = acc[0][mi][nj][half * 2 + 0];
                    const float gy = acc[0][mi][nj][half * 2 + 1];
                    const float ux = acc[1][mi][nj][half * 2 + 0];
                    const float uy = acc[1][mi][nj][half * 2 + 1];
                    const float hx = wt * ux * (gx / (1.f + __expf(-gx)));
                    const float hy = wt * uy * (gy / (1.f + __expf(-gy)));
                    __nv_bfloat162 hh = __floats2bfloat162_rn(hx, hy);
                    const float2 fh = __bfloat1622float2(hh);
                    __nv_bfloat162 hl = __floats2bfloat162_rn(hx - fh.x, hy - fh.y);
                    g_Hhi[base + nj * 4] = *(uint32_t*)&hh;
                    g_Hlo[base + nj * 4] = *(uint32_t*)&hl;
                }
            }
        }
    }
}

// ================= down GEMM (cp.async 3-stage, scatter-add epilogue) =================
// Tile M=128 x N=128. K=768, chunk 32. Stage: A_hi 0 | A_lo 10240 | B_hi 20480 | B_lo 30720.
#define DN_SMEM (3 * 40960)
__global__ __launch_bounds__(256, 1)
void dn_kernel(float* __restrict__ out) {
    constexpr int NC = FDIM / 32;
    extern __shared__ char smem[];

    const int tid = threadIdx.x;
    const int lane = tid & 31, wid = tid >> 5;
    const int wm = wid >> 2, wn = wid & 3;

    const int e  = blockIdx.y / MTILES;
    const int mt = blockIdx.y % MTILES;
    int segBeg = g_off[e], segEnd = g_off[e + 1];
    if (segBeg < 0) segBeg = 0;
    if (segEnd > NSLOT) segEnd = NSLOT;
    const int m0 = segBeg + mt * 128;
    if (m0 >= segEnd) return;
    const int mrem = segEnd - m0;
    const int n0 = blockIdx.x * 128;

    const uint32_t sb = smem_u32(smem);
    const int arow = tid >> 1, acg = tid & 1;

    auto ISSUE = [&](int c) {
        const uint32_t st = sb + (uint32_t)(c % 3) * 40960u;
        const int k0 = c * 32;
        {   // A: h split, slot-indexed
            const uint32_t sz = (arow < mrem) ? 16u : 0u;
            const int r = m0 + ((arow < mrem) ? arow : 0);
            const size_t ao = (((size_t)r * FDIM + k0) >> 1) + (size_t)acg * 8;
            const uint32_t da = st + (uint32_t)(arow * 80 + acg * 32);
            const uint64_t sh = __cvta_generic_to_global((const void*)(g_Hhi + ao));
            const uint64_t sl = __cvta_generic_to_global((const void*)(g_Hlo + ao));
            CP16(da,              sh,      sz);
            CP16(da + 16,         sh + 16, sz);
            CP16(da + 10240,      sl,      sz);
            CP16(da + 10240 + 16, sl + 16, sz);
        }
        {   // B: down weights (slice 2)
            const size_t bo = WSZ + ((((size_t)e * DIM + n0 + arow) * FDIM + k0) >> 1) + (size_t)acg * 8;
            const uint32_t db = st + 20480u + (uint32_t)(arow * 80 + acg * 32);
            const uint64_t sh = __cvta_generic_to_global((const void*)(g_Whi + bo));
            const uint64_t sl = __cvta_generic_to_global((const void*)(g_Wlo + bo));
            CP16(db,              sh,      16u);
            CP16(db + 16,         sh + 16, 16u);
            CP16(db + 10240,      sl,      16u);
            CP16(db + 10240 + 16, sl + 16, 16u);
        }
        CP_COMMIT();
    };

    float acc[4][4][4];
    #pragma unroll
    for (int i = 0; i < 4; i++)
        #pragma unroll
        for (int j = 0; j < 4; j++)
            #pragma unroll
            for (int k = 0; k < 4; k++) acc[i][j][k] = 0.f;

    const int lr = lane & 15, lh = lane >> 4;
    const uint32_t aoffw = (uint32_t)((wm * 64 + lr) * 80 + lh * 16);
    const uint32_t boffw = (uint32_t)(20480 + (wn * 32 + lr) * 80 + lh * 16);

    ISSUE(0); ISSUE(1);
    for (int c = 0; c < NC; c++) {
        if (c + 1 < NC) { CP_WAIT1(); } else { CP_WAIT0(); }
        __syncthreads();
        const uint32_t st = sb + (uint32_t)(c % 3) * 40960u;
        #pragma unroll
        for (int ks = 0; ks < 2; ks++) {
            uint32_t ah[4][4], al[4][4], bh[2][4], bl[2][4];
            #pragma unroll
            for (int mi = 0; mi < 4; mi++) {
                ldm4(ah[mi], st + aoffw + mi * 16 * 80 + ks * 32);
                ldm4(al[mi], st + 10240 + aoffw + mi * 16 * 80 + ks * 32);
            }
            #pragma unroll
            for (int ni = 0; ni < 2; ni++) {
                ldm4(bh[ni], st + boffw + ni * 16 * 80 + ks * 32);
                ldm4(bl[ni], st + 10240 + boffw + ni * 16 * 80 + ks * 32);
            }
            #pragma unroll
            for (int mi = 0; mi < 4; mi++)
                #pragma unroll
                for (int ni = 0; ni < 2; ni++)
                    #pragma unroll
                    for (int j = 0; j < 2; j++)
                        mma16816(acc[mi][ni * 2 + j], ah[mi], bh[ni][j], bh[ni][j + 2]);
            #pragma unroll
            for (int mi = 0; mi < 4; mi++)
                #pragma unroll
                for (int ni = 0; ni < 2; ni++)
                    #pragma unroll
                    for (int j = 0; j < 2; j++)
                        mma16816(acc[mi][ni * 2 + j], ah[mi], bl[ni][j], bl[ni][j + 2]);
            #pragma unroll
            for (int mi = 0; mi < 4; mi++)
                #pragma unroll
                for (int ni = 0; ni < 2; ni++)
                    #pragma unroll
                    for (int j = 0; j < 2; j++)
                        mma16816(acc[mi][ni * 2 + j], al[mi], bh[ni][j], bh[ni][j + 2]);
        }
        if (c + 2 < NC) ISSUE(c + 2);
        __syncthreads();
    }

    // ---- epilogue: scatter-add (proven mapping) ----
    const int t4 = lane >> 2, t2 = (lane & 3) * 2;
    #pragma unroll
    for (int mi = 0; mi < 4; mi++) {
        #pragma unroll
        for (int half = 0; half < 2; half++) {
            const int row = wm * 64 + mi * 16 + t4 + half * 8;
            if (row < mrem) {
                int tok = g_perm[m0 + row];
                if (tok < 0) tok = 0;
                if (tok >= T_TOK) tok = T_TOK - 1;
                float* orow = out + (size_t)tok * DIM + n0 + wn * 32;
                #pragma unroll
                for (int nj = 0; nj < 4; nj++) {
                    atomicAdd(orow + nj * 8 + t2,     acc[mi][nj][half * 2 + 0]);
                    atomicAdd(orow + nj * 8 + t2 + 1, acc[mi][nj][half * 2 + 1]);
                }
            }
        }
    }
}

// ---------------- launch ----------------
extern "C" void kernel_launch(void* const* d_in, const int* in_sizes, int n_in,
                              void* d_out, int out_size) {
    long long smax = -1;
    for (int i = 0; i < n_in; i++)
        if ((long long)in_sizes[i] > smax) smax = in_sizes[i];
    const float* w3[3] = {0, 0, 0};
    int wpos[3] = {-1, -1, -1};
    int nw = 0, ih = -1, irt = -1;
    for (int i = 0; i < n_in; i++)
        if ((long long)in_sizes[i] == smax && nw < 3) { w3[nw] = (const float*)d_in[i]; wpos[nw] = i; nw++; }
    long long best_h = -1;
    for (int i = 0; i < n_in; i++) {
        if (i == wpos[0] || i == wpos[1] || i == wpos[2]) continue;
        if ((long long)in_sizes[i] > best_h) { best_h = in_sizes[i]; ih = i; }
    }
    long long best_r = (long long)1 << 62;
    for (int i = 0; i < n_in; i++) {
        if (i == wpos[0] || i == wpos[1] || i == wpos[2] || i == ih) continue;
        if ((long long)in_sizes[i] < best_r) { best_r = in_sizes[i]; irt = i; }
    }
    const float* x  = (ih  >= 0) ? (const float*)d_in[ih]  : (const float*)d_in[0];
    const float* rw = (irt >= 0) ? (const float*)d_in[irt] : (const float*)d_in[1];
    const float *gw, *uw, *dw;
    if (nw == 3) {
        if (ih == 2) { dw = w3[0]; gw = w3[1]; uw = w3[2]; }
        else         { gw = w3[0]; uw = w3[1]; dw = w3[2]; }
    } else {
        x  = (const float*)d_in[0]; rw = (const float*)d_in[1];
        gw = (const float*)d_in[2]; uw = (const float*)d_in[3]; dw = (const float*)d_in[4];
    }
    float* out = (float*)d_out;

    const int need = T_TOK * DIM + T_TOK * NEXP;
    const int write_logits = (out_size >= need) ? 1 : 0;
    float* logits = out + (size_t)T_TOK * DIM;

    cudaFuncSetAttribute(gu_kernel, cudaFuncAttributeMaxDynamicSharedMemorySize, GU_SMEM);
    cudaFuncSetAttribute(dn_kernel, cudaFuncAttributeMaxDynamicSharedMemorySize, DN_SMEM);

    zero_out_kernel<<<(T_TOK * DIM / 4 + 255) / 256, 256>>>(out);
    conv_all_kernel<<<dim3(4096, 3), 256>>>((const float4*)gw, (const float4*)uw, (const float4*)dw);
    xsplit_kernel<<<(T_TOK * DIM / 4 + 255) / 256, 256>>>((const float4*)x);
    router_kernel<<<T_TOK, 256>>>(x, rw, logits, write_logits);
    route_build_kernel<<<1, 512>>>();

    gu_kernel<<<dim3(FDIM / 64, NEXP * MTILES), 256, GU_SMEM>>>();
    dn_kernel<<<dim3(DIM / 128, NEXP * MTILES), 256, DN_SMEM>>>(out);
}

// round 12
// speedup vs baseline: 12.2795x; 2.2132x over previous
#include <cuda_runtime.h>
#include <cuda_fp16.h>
#include <math.h>
#include <stdint.h>

#define T_TOK 4096
#define DIM   2048
#define NEXP  16
#define FDIM  768
#define NSLOT (T_TOK * 2)
#define MTILES 64
#define WSZ ((size_t)NEXP * FDIM * DIM)

// ---------------- device scratch; NEVER passed as kernel args (ATS host-shadow hazard) ----------------
__device__ __align__(16) int      g_off[NEXP + 1];
__device__ __align__(16) int      g_tok_e[NSLOT];
__device__ __align__(16) float    g_tok_w[NSLOT];
__device__ __align__(16) int      g_perm[NSLOT];
__device__ __align__(16) float    g_wt[NSLOT];
__device__ __align__(16) uint32_t g_Wh[3 * WSZ / 2];              // fp16x2: [gate|up|down]
__device__ __align__(16) uint32_t g_Xh[(size_t)T_TOK * DIM / 2];  // x fp16
__device__ __align__(16) uint32_t g_Hh[(size_t)NSLOT * FDIM / 2]; // h fp16

// ---------------- helpers ----------------
__device__ __forceinline__ uint32_t smem_u32(const void* p) {
    uint32_t a;
    asm("{ .reg .u64 t; cvta.to.shared.u64 t, %1; cvt.u32.u64 %0, t; }" : "=r"(a) : "l"(p));
    return a;
}
#define CP16(dst, src, sz) \
    asm volatile("cp.async.cg.shared.global [%0], [%1], 16, %2;" \
        :: "r"(dst), "l"(src), "r"(sz) : "memory")
#define CP_COMMIT() asm volatile("cp.async.commit_group;" ::: "memory")
#define CP_WAIT1()  asm volatile("cp.async.wait_group 1;" ::: "memory")
#define CP_WAIT0()  asm volatile("cp.async.wait_group 0;" ::: "memory")

__device__ __forceinline__ void ldm4(uint32_t* r, uint32_t addr) {
    asm volatile("ldmatrix.sync.aligned.m8n8.x4.shared.b16 {%0,%1,%2,%3}, [%4];"
        : "=r"(r[0]), "=r"(r[1]), "=r"(r[2]), "=r"(r[3]) : "r"(addr));
}
__device__ __forceinline__ void mma16816(float* d, const uint32_t* a, uint32_t b0, uint32_t b1) {
    asm volatile(
        "mma.sync.aligned.m16n8k16.row.col.f32.f16.f16.f32 "
        "{%0,%1,%2,%3}, {%4,%5,%6,%7}, {%8,%9}, {%0,%1,%2,%3};"
        : "+f"(d[0]), "+f"(d[1]), "+f"(d[2]), "+f"(d[3])
        : "r"(a[0]), "r"(a[1]), "r"(a[2]), "r"(a[3]), "r"(b0), "r"(b1));
}

// ---------------- zero output ----------------
__global__ void zero_out_kernel(float* __restrict__ out) {
    const size_t i = (size_t)blockIdx.x * blockDim.x + threadIdx.x;
    if (i < (size_t)T_TOK * DIM / 4)
        ((float4*)out)[i] = make_float4(0.f, 0.f, 0.f, 0.f);
}

// ---------------- all-weights fp32 -> fp16 in ONE launch (grid.y = slice) ----------------
__global__ void conv_all_kernel(const float4* __restrict__ gw,
                                const float4* __restrict__ uw,
                                const float4* __restrict__ dw) {
    const int slice = blockIdx.y;
    const float4* src = (slice == 0) ? gw : (slice == 1) ? uw : dw;
    const size_t base = (size_t)slice * (WSZ / 2);
    const size_t n4 = WSZ / 4;
    for (size_t i = (size_t)blockIdx.x * blockDim.x + threadIdx.x; i < n4;
         i += (size_t)gridDim.x * blockDim.x) {
        const float4 v = src[i];
        __half2 h0 = __floats2half2_rn(v.x, v.y);
        __half2 h1 = __floats2half2_rn(v.z, v.w);
        uint2 u;
        u.x = *(uint32_t*)&h0; u.y = *(uint32_t*)&h1;
        *(uint2*)&g_Wh[base + 2 * i] = u;
    }
}

// ---------------- x fp32 -> fp16 ----------------
__global__ void xhalf_kernel(const float4* __restrict__ src) {
    const size_t n4 = (size_t)T_TOK * DIM / 4;
    const size_t i = (size_t)blockIdx.x * blockDim.x + threadIdx.x;
    if (i >= n4) return;
    const float4 v = src[i];
    __half2 h0 = __floats2half2_rn(v.x, v.y);
    __half2 h1 = __floats2half2_rn(v.z, v.w);
    uint2 u;
    u.x = *(uint32_t*)&h0; u.y = *(uint32_t*)&h1;
    *(uint2*)&g_Xh[2 * i] = u;
}

// ---------------- router (proven) ----------------
__global__ __launch_bounds__(256)
void router_kernel(const float* __restrict__ x,
                   const float* __restrict__ rw,
                   float* __restrict__ logits_out,
                   int write_logits) {
    __shared__ float xs[DIM];
    __shared__ float lg[NEXP];
    const int t = blockIdx.x;
    const int tid = threadIdx.x;
    const int warp = tid >> 5, lane = tid & 31;

    const float4* xg = (const float4*)(x + (size_t)t * DIM);
    for (int i = tid; i < DIM / 4; i += 256) ((float4*)xs)[i] = xg[i];
    __syncthreads();
    {
        const float4* w0 = (const float4*)(rw + (size_t)(warp * 2) * DIM);
        const float4* w1 = (const float4*)(rw + (size_t)(warp * 2 + 1) * DIM);
        float a0 = 0.f, a1 = 0.f;
        for (int i = lane; i < DIM / 4; i += 32) {
            const float4 xv = ((const float4*)xs)[i];
            const float4 va = w0[i];
            const float4 vb = w1[i];
            a0 += xv.x * va.x + xv.y * va.y + xv.z * va.z + xv.w * va.w;
            a1 += xv.x * vb.x + xv.y * vb.y + xv.z * vb.z + xv.w * vb.w;
        }
        #pragma unroll
        for (int o = 16; o > 0; o >>= 1) {
            a0 += __shfl_xor_sync(0xffffffffu, a0, o);
            a1 += __shfl_xor_sync(0xffffffffu, a1, o);
        }
        if (lane == 0) { lg[warp * 2] = a0; lg[warp * 2 + 1] = a1; }
    }
    __syncthreads();
    if (write_logits && tid < NEXP)
        logits_out[(size_t)t * NEXP + tid] = lg[tid];
    if (tid == 0) {
        int i0 = 0;
        #pragma unroll
        for (int i = 1; i < NEXP; i++)
            if (lg[i] > lg[i0]) i0 = i;
        int i1 = (i0 == 0) ? 1 : 0;
        #pragma unroll
        for (int i = 0; i < NEXP; i++) {
            if (i == i0) continue;
            if (lg[i] > lg[i1]) i1 = i;
        }
        const float e1 = __expf(lg[i1] - lg[i0]);
        const float s = 1.0f + e1;
        g_tok_e[2 * t + 0] = i0; g_tok_w[2 * t + 0] = 1.0f / s;
        g_tok_e[2 * t + 1] = i1; g_tok_w[2 * t + 1] = e1 / s;
    }
}

// ---------------- compaction (proven) ----------------
__global__ void route_build_kernel() {
    __shared__ int s_cnt[NEXP];
    __shared__ int s_off[NEXP + 1];
    const int tid = threadIdx.x;
    if (tid < NEXP) s_cnt[tid] = 0;
    __syncthreads();
    for (int i = tid; i < NSLOT; i += 512)
        atomicAdd(&s_cnt[g_tok_e[i] & (NEXP - 1)], 1);
    __syncthreads();
    if (tid == 0) {
        int off = 0;
        #pragma unroll
        for (int e = 0; e < NEXP; e++) { s_off[e] = off; g_off[e] = off; off += s_cnt[e]; }
        s_off[NEXP] = off; g_off[NEXP] = off;
    }
    __syncthreads();
    const int warp = tid >> 5, lane = tid & 31;
    int base = s_off[warp];
    for (int i0 = 0; i0 < NSLOT; i0 += 32) {
        const int i = i0 + lane;
        const bool m = ((g_tok_e[i] & (NEXP - 1)) == warp);
        const unsigned mask = __ballot_sync(0xffffffffu, m);
        if (m) {
            const int pos = base + __popc(mask & ((1u << lane) - 1u));
            if (pos < NSLOT) {
                g_perm[pos] = i >> 1;
                g_wt[pos]   = g_tok_w[i];
            }
        }
        base += __popc(mask);
    }
}

// ================= fused gate+up fp16 GEMM with in-register SwiGLU epilogue =================
// Tile M=128 x N=64 for BOTH gate and up. K=2048, chunk 32, 3-stage cp.async.
// Stage 20480 B: A 0..10240 | Bg 10240..15360 | Bu 15360..20480 (80 B row stride).
#define GU_SMEM (3 * 20480)
__global__ __launch_bounds__(256, 2)
void gu_kernel() {
    constexpr int NC = DIM / 32;
    extern __shared__ char smem[];
    __shared__ int   s_rows[128];
    __shared__ float s_w[128];

    const int tid = threadIdx.x;
    const int lane = tid & 31, wid = tid >> 5;
    const int wm = wid >> 1, wn = wid & 1;          // 4 x 2 warps; warp tile 32 x 32 per matrix

    const int e  = blockIdx.y / MTILES;
    const int mt = blockIdx.y % MTILES;
    int segBeg = g_off[e], segEnd = g_off[e + 1];
    if (segBeg < 0) segBeg = 0;
    if (segEnd > NSLOT) segEnd = NSLOT;
    const int m0 = segBeg + mt * 128;
    if (m0 >= segEnd) return;
    const int mrem = segEnd - m0;
    const int n0 = blockIdx.x * 64;

    if (tid < 128) {
        const int idx = m0 + tid;
        int r = -1; float w = 0.f;
        if (idx < segEnd) {
            r = g_perm[idx];
            if (r < 0) r = 0;
            if (r >= T_TOK) r = T_TOK - 1;
            w = g_wt[idx];
        }
        s_rows[tid] = r; s_w[tid] = w;
    }
    __syncthreads();

    const uint32_t sb = smem_u32(smem);
    const int arow = tid >> 1, acg = tid & 1;

    auto ISSUE = [&](int c) {
        const uint32_t st = sb + (uint32_t)(c % 3) * 20480u;
        const int k0 = c * 32;
        {   // A: gathered x fp16
            const int r = s_rows[arow];
            const uint32_t sz = (r >= 0) ? 16u : 0u;
            const size_t ao = (((size_t)(r < 0 ? 0 : r) * DIM + k0) >> 1) + (size_t)acg * 8;
            const uint32_t da = st + (uint32_t)(arow * 80 + acg * 32);
            const uint64_t sa = __cvta_generic_to_global((const void*)(g_Xh + ao));
            CP16(da,      sa,      sz);
            CP16(da + 16, sa + 16, sz);
        }
        {   // B: gate rows 0-63, up rows 64-127
            const int gu = arow >> 6;
            const int row = arow & 63;
            const size_t bo = (size_t)gu * (WSZ / 2)
                            + ((((size_t)e * FDIM + n0 + row) * DIM + k0) >> 1) + (size_t)acg * 8;
            const uint32_t db = st + 10240u + (uint32_t)(gu * 5120 + row * 80 + acg * 32);
            const uint64_t sb2 = __cvta_generic_to_global((const void*)(g_Wh + bo));
            CP16(db,      sb2,      16u);
            CP16(db + 16, sb2 + 16, 16u);
        }
        CP_COMMIT();
    };

    float acc[2][2][4][4];   // [gu][mi][n-frag][4]
    #pragma unroll
    for (int a = 0; a < 2; a++)
        #pragma unroll
        for (int b = 0; b < 2; b++)
            #pragma unroll
            for (int cN = 0; cN < 4; cN++)
                #pragma unroll
                for (int d = 0; d < 4; d++) acc[a][b][cN][d] = 0.f;

    const int lr = lane & 15, lh = lane >> 4;

    ISSUE(0); ISSUE(1);
    for (int c = 0; c < NC; c++) {
        if (c + 1 < NC) { CP_WAIT1(); } else { CP_WAIT0(); }
        __syncthreads();
        const uint32_t st = sb + (uint32_t)(c % 3) * 20480u;
        #pragma unroll
        for (int ks = 0; ks < 2; ks++) {
            uint32_t ah[2][4], bh[2][2][4];
            #pragma unroll
            for (int mi = 0; mi < 2; mi++)
                ldm4(ah[mi], st + (uint32_t)((wm * 32 + mi * 16 + lr) * 80 + ks * 32 + lh * 16));
            #pragma unroll
            for (int gu = 0; gu < 2; gu++)
                #pragma unroll
                for (int ni = 0; ni < 2; ni++)
                    ldm4(bh[gu][ni], st + 10240u + (uint32_t)(gu * 5120
                        + (wn * 32 + ni * 16 + lr) * 80 + ks * 32 + lh * 16));
            // 16 independent accumulators -> no RAW chains
            #pragma unroll
            for (int gu = 0; gu < 2; gu++)
                #pragma unroll
                for (int mi = 0; mi < 2; mi++)
                    #pragma unroll
                    for (int ni = 0; ni < 2; ni++)
                        #pragma unroll
                        for (int j = 0; j < 2; j++)
                            mma16816(acc[gu][mi][ni * 2 + j], ah[mi], bh[gu][ni][j], bh[gu][ni][j + 2]);
        }
        if (c + 2 < NC) ISSUE(c + 2);
        __syncthreads();
    }

    // ---- epilogue: h = wt * silu(g) * u -> fp16 -> g_Hh ----
    const int t4 = lane >> 2, l3 = lane & 3;
    #pragma unroll
    for (int mi = 0; mi < 2; mi++) {
        #pragma unroll
        for (int half = 0; half < 2; half++) {
            const int row = wm * 32 + mi * 16 + t4 + half * 8;
            if (row < mrem) {
                const float wt = s_w[row];
                const size_t base = (size_t)(m0 + row) * (FDIM / 2) + (size_t)((n0 + wn * 32) >> 1) + l3;
                #pragma unroll
                for (int nj = 0; nj < 4; nj++) {
                    const float gx = acc[0][mi][nj][half * 2 + 0];
                    const float gy = acc[0][mi][nj][half * 2 + 1];
                    const float ux = acc[1][mi][nj][half * 2 + 0];
                    const float uy = acc[1][mi][nj][half * 2 + 1];
                    const float hx = wt * ux * (gx / (1.f + __expf(-gx)));
                    const float hy = wt * uy * (gy / (1.f + __expf(-gy)));
                    __half2 hh = __floats2half2_rn(hx, hy);
                    g_Hh[base + nj * 4] = *(uint32_t*)&hh;
                }
            }
        }
    }
}

// ================= down fp16 GEMM (cp.async 3-stage, scatter-add epilogue) =================
// Tile M=128 x N=128. K=768, chunk 32. Stage 20480 B: A 0..10240 | B 10240..20480.
#define DN_SMEM (3 * 20480)
__global__ __launch_bounds__(256, 2)
void dn_kernel(float* __restrict__ out) {
    constexpr int NC = FDIM / 32;
    extern __shared__ char smem[];

    const int tid = threadIdx.x;
    const int lane = tid & 31, wid = tid >> 5;
    const int wm = wid >> 2, wn = wid & 3;

    const int e  = blockIdx.y / MTILES;
    const int mt = blockIdx.y % MTILES;
    int segBeg = g_off[e], segEnd = g_off[e + 1];
    if (segBeg < 0) segBeg = 0;
    if (segEnd > NSLOT) segEnd = NSLOT;
    const int m0 = segBeg + mt * 128;
    if (m0 >= segEnd) return;
    const int mrem = segEnd - m0;
    const int n0 = blockIdx.x * 128;

    const uint32_t sb = smem_u32(smem);
    const int arow = tid >> 1, acg = tid & 1;

    auto ISSUE = [&](int c) {
        const uint32_t st = sb + (uint32_t)(c % 3) * 20480u;
        const int k0 = c * 32;
        {   // A: h fp16, slot-indexed
            const uint32_t sz = (arow < mrem) ? 16u : 0u;
            const int r = m0 + ((arow < mrem) ? arow : 0);
            const size_t ao = (((size_t)r * FDIM + k0) >> 1) + (size_t)acg * 8;
            const uint32_t da = st + (uint32_t)(arow * 80 + acg * 32);
            const uint64_t sa = __cvta_generic_to_global((const void*)(g_Hh + ao));
            CP16(da,      sa,      sz);
            CP16(da + 16, sa + 16, sz);
        }
        {   // B: down weights (slice 2 at uint32 offset WSZ)
            const size_t bo = WSZ + ((((size_t)e * DIM + n0 + arow) * FDIM + k0) >> 1) + (size_t)acg * 8;
            const uint32_t db = st + 10240u + (uint32_t)(arow * 80 + acg * 32);
            const uint64_t sb2 = __cvta_generic_to_global((const void*)(g_Wh + bo));
            CP16(db,      sb2,      16u);
            CP16(db + 16, sb2 + 16, 16u);
        }
        CP_COMMIT();
    };

    float acc[4][4][4];
    #pragma unroll
    for (int i = 0; i < 4; i++)
        #pragma unroll
        for (int j = 0; j < 4; j++)
            #pragma unroll
            for (int k = 0; k < 4; k++) acc[i][j][k] = 0.f;

    const int lr = lane & 15, lh = lane >> 4;
    const uint32_t aoffw = (uint32_t)((wm * 64 + lr) * 80 + lh * 16);
    const uint32_t boffw = (uint32_t)(10240 + (wn * 32 + lr) * 80 + lh * 16);

    ISSUE(0); ISSUE(1);
    for (int c = 0; c < NC; c++) {
        if (c + 1 < NC) { CP_WAIT1(); } else { CP_WAIT0(); }
        __syncthreads();
        const uint32_t st = sb + (uint32_t)(c % 3) * 20480u;
        #pragma unroll
        for (int ks = 0; ks < 2; ks++) {
            uint32_t ah[4][4], bh[2][4];
            #pragma unroll
            for (int mi = 0; mi < 4; mi++)
                ldm4(ah[mi], st + aoffw + mi * 16 * 80 + ks * 32);
            #pragma unroll
            for (int ni = 0; ni < 2; ni++)
                ldm4(bh[ni], st + boffw + ni * 16 * 80 + ks * 32);
            #pragma unroll
            for (int mi = 0; mi < 4; mi++)
                #pragma unroll
                for (int ni = 0; ni < 2; ni++)
                    #pragma unroll
                    for (int j = 0; j < 2; j++)
                        mma16816(acc[mi][ni * 2 + j], ah[mi], bh[ni][j], bh[ni][j + 2]);
        }
        if (c + 2 < NC) ISSUE(c + 2);
        __syncthreads();
    }

    // ---- epilogue: scatter-add (proven mapping) ----
    const int t4 = lane >> 2, t2 = (lane & 3) * 2;
    #pragma unroll
    for (int mi = 0; mi < 4; mi++) {
        #pragma unroll
        for (int half = 0; half < 2; half++) {
            const int row = wm * 64 + mi * 16 + t4 + half * 8;
            if (row < mrem) {
                int tok = g_perm[m0 + row];
                if (tok < 0) tok = 0;
                if (tok >= T_TOK) tok = T_TOK - 1;
                float* orow = out + (size_t)tok * DIM + n0 + wn * 32;
                #pragma unroll
                for (int nj = 0; nj < 4; nj++) {
                    atomicAdd(orow + nj * 8 + t2,     acc[mi][nj][half * 2 + 0]);
                    atomicAdd(orow + nj * 8 + t2 + 1, acc[mi][nj][half * 2 + 1]);
                }
            }
        }
    }
}

// ---------------- launch ----------------
extern "C" void kernel_launch(void* const* d_in, const int* in_sizes, int n_in,
                              void* d_out, int out_size) {
    long long smax = -1;
    for (int i = 0; i < n_in; i++)
        if ((long long)in_sizes[i] > smax) smax = in_sizes[i];
    const float* w3[3] = {0, 0, 0};
    int wpos[3] = {-1, -1, -1};
    int nw = 0, ih = -1, irt = -1;
    for (int i = 0; i < n_in; i++)
        if ((long long)in_sizes[i] == smax && nw < 3) { w3[nw] = (const float*)d_in[i]; wpos[nw] = i; nw++; }
    long long best_h = -1;
    for (int i = 0; i < n_in; i++) {
        if (i == wpos[0] || i == wpos[1] || i == wpos[2]) continue;
        if ((long long)in_sizes[i] > best_h) { best_h = in_sizes[i]; ih = i; }
    }
    long long best_r = (long long)1 << 62;
    for (int i = 0; i < n_in; i++) {
        if (i == wpos[0] || i == wpos[1] || i == wpos[2] || i == ih) continue;
        if ((long long)in_sizes[i] < best_r) { best_r = in_sizes[i]; irt = i; }
    }
    const float* x  = (ih  >= 0) ? (const float*)d_in[ih]  : (const float*)d_in[0];
    const float* rw = (irt >= 0) ? (const float*)d_in[irt] : (const float*)d_in[1];
    const float *gw, *uw, *dw;
    if (nw == 3) {
        if (ih == 2) { dw = w3[0]; gw = w3[1]; uw = w3[2]; }
        else         { gw = w3[0]; uw = w3[1]; dw = w3[2]; }
    } else {
        x  = (const float*)d_in[0]; rw = (const float*)d_in[1];
        gw = (const float*)d_in[2]; uw = (const float*)d_in[3]; dw = (const float*)d_in[4];
    }
    float* out = (float*)d_out;

    const int need = T_TOK * DIM + T_TOK * NEXP;
    const int write_logits = (out_size >= need) ? 1 : 0;
    float* logits = out + (size_t)T_TOK * DIM;

    cudaFuncSetAttribute(gu_kernel, cudaFuncAttributeMaxDynamicSharedMemorySize, GU_SMEM);
    cudaFuncSetAttribute(dn_kernel, cudaFuncAttributeMaxDynamicSharedMemorySize, DN_SMEM);

    zero_out_kernel<<<(T_TOK * DIM / 4 + 255) / 256, 256>>>(out);
    conv_all_kernel<<<dim3(4096, 3), 256>>>((const float4*)gw, (const float4*)uw, (const float4*)dw);
    xhalf_kernel<<<(T_TOK * DIM / 4 + 255) / 256, 256>>>((const float4*)x);
    router_kernel<<<T_TOK, 256>>>(x, rw, logits, write_logits);
    route_build_kernel<<<1, 512>>>();

    gu_kernel<<<dim3(FDIM / 64, NEXP * MTILES), 256, GU_SMEM>>>();
    dn_kernel<<<dim3(DIM / 128, NEXP * MTILES), 256, DN_SMEM>>>(out);
}